// round 1
// baseline (speedup 1.0000x reference)
#include <cuda_runtime.h>
#include <cstdint>

// ---------------- problem constants ----------------
constexpr int P_   = 64;                 // proposals
constexpr int D2c  = 32, H2c = 64, W2c = 64;   // comb2 spatial
constexpr int NV2  = D2c * H2c * W2c;    // 131072 voxels, comb2 channel stride
constexpr int C1STRIDE = 64 * 128 * 128; // out1 channel stride (1048576)
constexpr int S4 = 12, S2 = 24;
constexpr int V4 = S4 * S4 * S4;         // 1728
constexpr int Vc = S2 * S2 * S2;         // 13824
constexpr float EPSN = 1e-5f;

// ---------------- scratch (static device memory; no allocs) ----------------
__device__ float g_T[P_ * 64 * V4];                       // low-res up2 conv result
__device__ float g_U[(long long)P_ * 64 * Vc];            // upsampled (pre-norm)
__device__ float g_F[(long long)P_ * 64 * Vc];            // back2 conv (pre-norm)
__device__ float g_st1[P_ * 64 * 2];                      // sum/sumsq of U
__device__ float g_st2[P_ * 64 * 2];                      // sum/sumsq of F
__device__ float g_CR[P_ * 64 * 512];                     // pooled crops (= fc1 input rows)
__device__ float g_X1p[16 * P_ * 512];                    // fc1 K-split partials
__device__ float g_X1[P_ * 512];                          // fc1 out (post relu)
__device__ float g_X2[P_ * 256];                          // fc2 out (post relu)

// ---------------- helpers ----------------
__device__ __forceinline__ void breduce2(float& s, float& ss) {
    __shared__ float bs[16], bss[16];
    #pragma unroll
    for (int off = 16; off; off >>= 1) {
        s  += __shfl_down_sync(0xffffffffu, s,  off);
        ss += __shfl_down_sync(0xffffffffu, ss, off);
    }
    int wrp = threadIdx.x >> 5, ln = threadIdx.x & 31;
    int nw = blockDim.x >> 5;
    if (ln == 0) { bs[wrp] = s; bss[wrp] = ss; }
    __syncthreads();
    if (wrp == 0) {
        s  = (ln < nw) ? bs[ln]  : 0.f;
        ss = (ln < nw) ? bss[ln] : 0.f;
        #pragma unroll
        for (int off = 16; off; off >>= 1) {
            s  += __shfl_down_sync(0xffffffffu, s,  off);
            ss += __shfl_down_sync(0xffffffffu, ss, off);
        }
    }
}

// ---------------- kernel A: RPN head ----------------
__global__ __launch_bounds__(256) void k_rpn(
    const float* __restrict__ comb2,
    const float* __restrict__ w_rpn, const float* __restrict__ b_rpn,
    const float* __restrict__ w_rlog, const float* __restrict__ b_rlog,
    const float* __restrict__ w_rdel, const float* __restrict__ b_rdel,
    float* __restrict__ out)
{
    __shared__ float ws[128 * 64];   // ws[c*64+o]
    __shared__ float wl[64 * 3];     // wl[o*3+a]
    __shared__ float wd[64 * 18];    // wd[o*18+j]
    __shared__ float sb[64], sbl[3], sbd[18];
    int tid = threadIdx.x;
    for (int i = tid; i < 128 * 64; i += 256) { int c = i >> 6, o = i & 63; ws[i] = w_rpn[o * 128 + c]; }
    for (int i = tid; i < 64 * 3;  i += 256) { int o = i / 3,  a = i - o * 3;  wl[i] = w_rlog[a * 64 + o]; }
    for (int i = tid; i < 64 * 18; i += 256) { int o = i / 18, j = i - o * 18; wd[i] = w_rdel[j * 64 + o]; }
    if (tid < 64) sb[tid]  = b_rpn[tid];
    if (tid < 3)  sbl[tid] = b_rlog[tid];
    if (tid < 18) sbd[tid] = b_rdel[tid];
    __syncthreads();

    int vox = blockIdx.x * 256 + tid;   // grid 512*256 == NV2 exactly
    float acc[64];
    #pragma unroll
    for (int o = 0; o < 64; o++) acc[o] = sb[o];
    for (int c = 0; c < 128; c++) {
        float v = __ldg(&comb2[c * NV2 + vox]);
        const float* w = &ws[c << 6];
        #pragma unroll
        for (int o = 0; o < 64; o++) acc[o] = fmaf(w[o], v, acc[o]);
    }
    float rl0 = sbl[0], rl1 = sbl[1], rl2 = sbl[2];
    float rd[18];
    #pragma unroll
    for (int j = 0; j < 18; j++) rd[j] = sbd[j];
    for (int o = 0; o < 64; o++) {
        float hv = fmaxf(acc[o], 0.f);
        rl0 = fmaf(wl[o * 3 + 0], hv, rl0);
        rl1 = fmaf(wl[o * 3 + 1], hv, rl1);
        rl2 = fmaf(wl[o * 3 + 2], hv, rl2);
        #pragma unroll
        for (int j = 0; j < 18; j++) rd[j] = fmaf(wd[o * 18 + j], hv, rd[j]);
    }
    out[vox * 3 + 0] = rl0; out[vox * 3 + 1] = rl1; out[vox * 3 + 2] = rl2;
    float* od = out + (long long)NV2 * 3 + (long long)vox * 18;
    #pragma unroll
    for (int j = 0; j < 18; j++) od[j] = rd[j];
}

// ---------------- kernel B: up2 conv at low resolution ----------------
// conv1x1 commutes with linear upsampling (interp weights sum to 1), bias included.
__global__ __launch_bounds__(256) void k_conv_low(
    const float* __restrict__ comb2, const int* __restrict__ props,
    const float* __restrict__ w_up2, const float* __restrict__ b_up2)
{
    __shared__ float ws[128 * 64];
    __shared__ float sb[64];
    int tid = threadIdx.x;
    for (int i = tid; i < 128 * 64; i += 256) { int c = i >> 6, o = i & 63; ws[i] = w_up2[o * 128 + c]; }
    if (tid < 64) sb[tid] = b_up2[tid];
    __syncthreads();

    int p = blockIdx.y;
    int vox = blockIdx.x * 256 + tid;
    if (vox >= V4) return;
    int z0 = props[p * 7 + 1] >> 2, y0 = props[p * 7 + 2] >> 2, x0 = props[p * 7 + 3] >> 2;
    int d = vox / 144; int r = vox - d * 144; int h = r / 12; int w = r - h * 12;
    int base = (z0 + d) * (H2c * W2c) + (y0 + h) * W2c + (x0 + w);

    float acc[64];
    #pragma unroll
    for (int o = 0; o < 64; o++) acc[o] = sb[o];
    for (int c = 0; c < 128; c++) {
        float v = __ldg(&comb2[c * NV2 + base]);
        const float* wp = &ws[c << 6];
        #pragma unroll
        for (int o = 0; o < 64; o++) acc[o] = fmaf(wp[o], v, acc[o]);
    }
    float* tp = &g_T[(p * 64) * V4 + vox];
    #pragma unroll
    for (int o = 0; o < 64; o++) tp[o * V4] = acc[o];
}

// ---------------- kernel C: trilinear upsample 12->24 + instnorm stats ----------------
__global__ __launch_bounds__(256) void k_upsample()
{
    int c = blockIdx.x, p = blockIdx.y;
    __shared__ float t[V4];
    const float* tp = &g_T[(p * 64 + c) * V4];
    for (int i = threadIdx.x; i < V4; i += 256) t[i] = tp[i];
    __syncthreads();

    float s = 0.f, ss = 0.f;
    float* up = &g_U[((long long)(p * 64 + c)) * Vc];
    for (int v = threadIdx.x; v < Vc; v += 256) {
        int Dq = v / 576; int r = v - Dq * 576; int Hq = r / 24; int Wq = r - Hq * 24;
        int nd = Dq * 11; int ld = nd / 23; float fd = (float)(nd - ld * 23) * (1.0f / 23.0f); int hd = min(ld + 1, 11);
        int nh = Hq * 11; int lh = nh / 23; float fh = (float)(nh - lh * 23) * (1.0f / 23.0f); int hh = min(lh + 1, 11);
        int nwc = Wq * 11; int lw = nwc / 23; float fw = (float)(nwc - lw * 23) * (1.0f / 23.0f); int hw = min(lw + 1, 11);
        const float* t0 = &t[ld * 144]; const float* t1 = &t[hd * 144];
        float a00 = t0[lh * 12 + lw], a01 = t0[lh * 12 + hw], a10 = t0[hh * 12 + lw], a11 = t0[hh * 12 + hw];
        float b00 = t1[lh * 12 + lw], b01 = t1[lh * 12 + hw], b10 = t1[hh * 12 + lw], b11 = t1[hh * 12 + hw];
        float ww0 = 1.f - fw, wh0 = 1.f - fh, wd0 = 1.f - fd;
        float i00 = a00 * ww0 + a01 * fw;
        float i01 = a10 * ww0 + a11 * fw;
        float i10 = b00 * ww0 + b01 * fw;
        float i11 = b10 * ww0 + b11 * fw;
        float j0 = i00 * wh0 + i01 * fh;
        float j1 = i10 * wh0 + i11 * fh;
        float val = j0 * wd0 + j1 * fd;
        up[v] = val;
        s += val;
        ss = fmaf(val, val, ss);
    }
    breduce2(s, ss);
    if (threadIdx.x == 0) { g_st1[(p * 64 + c) * 2] = s; g_st1[(p * 64 + c) * 2 + 1] = ss; }
}

// ---------------- kernel D: back2 conv (normalize u inline, read out1 crop) ----------------
__global__ __launch_bounds__(256) void k_back2(
    const float* __restrict__ out1, const int* __restrict__ props,
    const float* __restrict__ w_back2, const float* __restrict__ b_back2,
    const float* __restrict__ gam, const float* __restrict__ bet)
{
    __shared__ float ws[128 * 64];
    __shared__ float sb[64], sc[64], shf[64];
    int tid = threadIdx.x; int p = blockIdx.y;
    for (int i = tid; i < 128 * 64; i += 256) { int c = i >> 6, o = i & 63; ws[i] = w_back2[o * 128 + c]; }
    if (tid < 64) {
        sb[tid] = b_back2[tid];
        float s = g_st1[(p * 64 + tid) * 2], q = g_st1[(p * 64 + tid) * 2 + 1];
        float mean = s * (1.f / Vc);
        float var = q * (1.f / Vc) - mean * mean;
        float a = gam[tid] * rsqrtf(var + EPSN);
        sc[tid] = a; shf[tid] = bet[tid] - mean * a;
    }
    __syncthreads();

    int v = blockIdx.x * 256 + tid;   // 54*256 == 13824 exactly
    float acc[64];
    #pragma unroll
    for (int o = 0; o < 64; o++) acc[o] = sb[o];

    const float* Up = &g_U[(long long)p * 64 * Vc + v];
    for (int c = 0; c < 64; c++) {
        float u = fmaxf(fmaf(Up[(long long)c * Vc], sc[c], shf[c]), 0.f);
        const float* wp = &ws[c << 6];
        #pragma unroll
        for (int o = 0; o < 64; o++) acc[o] = fmaf(wp[o], u, acc[o]);
    }
    int z0 = props[p * 7 + 1] >> 1, y0 = props[p * 7 + 2] >> 1, x0 = props[p * 7 + 3] >> 1;
    int d = v / 576; int r = v - d * 576; int h = r / 24; int w = r - h * 24;
    const float* o1 = &out1[(long long)(z0 + d) * (128 * 128) + (y0 + h) * 128 + (x0 + w)];
    for (int c = 0; c < 64; c++) {
        float u = __ldg(&o1[(long long)c * C1STRIDE]);
        const float* wp = &ws[(64 + c) << 6];
        #pragma unroll
        for (int o = 0; o < 64; o++) acc[o] = fmaf(wp[o], u, acc[o]);
    }
    float* Fp = &g_F[(long long)p * 64 * Vc + v];
    #pragma unroll
    for (int o = 0; o < 64; o++) Fp[(long long)o * Vc] = acc[o];
}

// ---------------- kernel D2: instnorm stats of F ----------------
__global__ __launch_bounds__(256) void k_stats_F()
{
    int c = blockIdx.x, p = blockIdx.y;
    const float* q = &g_F[((long long)(p * 64 + c)) * Vc];
    float s = 0.f, ss = 0.f;
    for (int i = threadIdx.x; i < Vc; i += 256) { float v = q[i]; s += v; ss = fmaf(v, v, ss); }
    breduce2(s, ss);
    if (threadIdx.x == 0) { g_st2[(p * 64 + c) * 2] = s; g_st2[(p * 64 + c) * 2 + 1] = ss; }
}

// ---------------- kernel E: normalize + relu + 3^3 maxpool ----------------
__global__ __launch_bounds__(512) void k_pool(
    const float* __restrict__ gam, const float* __restrict__ bet)
{
    int o = blockIdx.x, p = blockIdx.y;
    float s = g_st2[(p * 64 + o) * 2], q = g_st2[(p * 64 + o) * 2 + 1];
    float mean = s * (1.f / Vc);
    float var = q * (1.f / Vc) - mean * mean;
    float a = gam[o] * rsqrtf(var + EPSN);
    float b = bet[o] - mean * a;

    int j = threadIdx.x;                 // 0..511
    int od = j >> 6; int r = j & 63; int oh = r >> 3; int ow = r & 7;
    const float* Fp = &g_F[((long long)(p * 64 + o)) * Vc];
    float m = -1e30f;
    #pragma unroll
    for (int dz = 0; dz < 3; dz++)
        #pragma unroll
        for (int dy = 0; dy < 3; dy++)
            #pragma unroll
            for (int dx = 0; dx < 3; dx++) {
                float v = Fp[(od * 3 + dz) * 576 + (oh * 3 + dy) * 24 + (ow * 3 + dx)];
                m = fmaxf(m, fmaxf(fmaf(v, a, b), 0.f));
            }
    g_CR[(p * 64 + o) * 512 + j] = m;
}

// ---------------- kernel F: fc1 GEMM  C[512,64] = W[512,32768] @ X^T, K-split ----------------
__global__ __launch_bounds__(256) void k_fc1(const float* __restrict__ w_fc1)
{
    __shared__ float Ws[64 * 65];
    __shared__ float Xs[64 * 65];
    int tid = threadIdx.x;
    int m0 = blockIdx.x * 64;        // 8 m-blocks
    int kb = blockIdx.y;             // 16 k-splits (2048 K each)
    int tp = tid & 63, tm = tid >> 6;

    float acc[16];
    #pragma unroll
    for (int i = 0; i < 16; i++) acc[i] = 0.f;

    for (int ch = 0; ch < 32; ch++) {
        int k0 = kb * 2048 + ch * 64;
        #pragma unroll
        for (int it = 0; it < 16; it++) {
            int idx = tid + it * 256;
            int kk = idx & 63, row = idx >> 6;
            Ws[row * 65 + kk] = w_fc1[(long long)(m0 + row) * 32768 + k0 + kk];
            Xs[kk * 65 + row] = g_CR[row * 32768 + k0 + kk];   // row == p
        }
        __syncthreads();
        #pragma unroll 8
        for (int k = 0; k < 64; k++) {
            float xv = Xs[k * 65 + tp];
            #pragma unroll
            for (int i = 0; i < 16; i++) acc[i] = fmaf(Ws[(tm * 16 + i) * 65 + k], xv, acc[i]);
        }
        __syncthreads();
    }
    float* outp = &g_X1p[((long long)kb * 64 + tp) * 512 + m0 + tm * 16];
    #pragma unroll
    for (int i = 0; i < 16; i++) outp[i] = acc[i];
}

// ---------------- kernel F2: deterministic K-split reduce + bias + relu ----------------
__global__ __launch_bounds__(512) void k_fc1red(const float* __restrict__ b_fc1)
{
    int p = blockIdx.x; int m = threadIdx.x;
    float s = b_fc1[m];
    #pragma unroll
    for (int kb = 0; kb < 16; kb++) s += g_X1p[((long long)kb * 64 + p) * 512 + m];
    g_X1[p * 512 + m] = fmaxf(s, 0.f);
}

// ---------------- kernel G: fc2 + relu ----------------
__global__ __launch_bounds__(256) void k_fc2(
    const float* __restrict__ w_fc2, const float* __restrict__ b_fc2)
{
    int p = blockIdx.x; int o = threadIdx.x;
    __shared__ float xs[512];
    for (int i = o; i < 512; i += 256) xs[i] = g_X1[p * 512 + i];
    __syncthreads();
    const float* wp = &w_fc2[o * 512];
    float s = b_fc2[o];
    #pragma unroll 8
    for (int k = 0; k < 512; k++) s = fmaf(wp[k], xs[k], s);
    g_X2[p * 256 + o] = fmaxf(s, 0.f);
}

// ---------------- kernel H: rcnn logits/deltas ----------------
__global__ __launch_bounds__(32) void k_heads(
    const float* __restrict__ w_logit, const float* __restrict__ b_logit,
    const float* __restrict__ w_delta, const float* __restrict__ b_delta,
    float* __restrict__ out)
{
    int p = blockIdx.x; int ln = threadIdx.x;
    const float* x = &g_X2[p * 256];
    const long long offL = (long long)NV2 * 21;  // after rpn logits+deltas
    for (int t = 0; t < 14; t++) {
        const float* wp = (t < 2) ? &w_logit[t * 256] : &w_delta[(t - 2) * 256];
        float s = 0.f;
        for (int k = ln; k < 256; k += 32) s = fmaf(wp[k], x[k], s);
        #pragma unroll
        for (int off = 16; off; off >>= 1) s += __shfl_down_sync(0xffffffffu, s, off);
        if (ln == 0) {
            if (t < 2) out[offL + p * 2 + t] = s + b_logit[t];
            else       out[offL + 128 + p * 12 + (t - 2)] = s + b_delta[t - 2];
        }
    }
}

// ---------------- launch ----------------
extern "C" void kernel_launch(void* const* d_in, const int* in_sizes, int n_in,
                              void* d_out, int out_size)
{
    const float* out1    = (const float*)d_in[0];
    const float* comb2   = (const float*)d_in[1];
    const int*   props   = (const int*)  d_in[2];
    const float* w_rpn   = (const float*)d_in[3];  const float* b_rpn   = (const float*)d_in[4];
    const float* w_rlog  = (const float*)d_in[5];  const float* b_rlog  = (const float*)d_in[6];
    const float* w_rdel  = (const float*)d_in[7];  const float* b_rdel  = (const float*)d_in[8];
    const float* w_up2   = (const float*)d_in[9];  const float* b_up2   = (const float*)d_in[10];
    const float* gu_up2  = (const float*)d_in[11]; const float* be_up2  = (const float*)d_in[12];
    const float* w_back2 = (const float*)d_in[13]; const float* b_back2 = (const float*)d_in[14];
    const float* gu_bk2  = (const float*)d_in[15]; const float* be_bk2  = (const float*)d_in[16];
    const float* w_fc1   = (const float*)d_in[17]; const float* b_fc1   = (const float*)d_in[18];
    const float* w_fc2   = (const float*)d_in[19]; const float* b_fc2   = (const float*)d_in[20];
    const float* w_logit = (const float*)d_in[21]; const float* b_logit = (const float*)d_in[22];
    const float* w_delta = (const float*)d_in[23]; const float* b_delta = (const float*)d_in[24];
    float* out = (float*)d_out;

    k_rpn<<<512, 256>>>(comb2, w_rpn, b_rpn, w_rlog, b_rlog, w_rdel, b_rdel, out);
    k_conv_low<<<dim3(7, P_), 256>>>(comb2, props, w_up2, b_up2);
    k_upsample<<<dim3(64, P_), 256>>>();
    k_back2<<<dim3(54, P_), 256>>>(out1, props, w_back2, b_back2, gu_up2, be_up2);
    k_stats_F<<<dim3(64, P_), 256>>>();
    k_pool<<<dim3(64, P_), 512>>>(gu_bk2, be_bk2);
    k_fc1<<<dim3(8, 16), 256>>>(w_fc1);
    k_fc1red<<<P_, 512>>>(b_fc1);
    k_fc2<<<P_, 256>>>(w_fc2, b_fc2);
    k_heads<<<P_, 32>>>(w_logit, b_logit, w_delta, b_delta, out);
}

// round 2
// speedup vs baseline: 1.1485x; 1.1485x over previous
#include <cuda_runtime.h>
#include <cstdint>

// ---------------- problem constants ----------------
constexpr int P_   = 64;
constexpr int NV2  = 32 * 64 * 64;        // comb2 voxels / channel stride
constexpr int C1STRIDE = 64 * 128 * 128;  // out1 channel stride
constexpr int V4 = 1728;                  // 12^3
constexpr int Vc = 13824;                 // 24^3
constexpr int NB2 = 108;                  // back2 n-tiles per proposal (13824/128)
constexpr float EPSN = 1e-5f;

typedef unsigned long long u64;

// ---------------- scratch ----------------
__device__ float g_T[P_ * 64 * V4];
__device__ float g_U[(long long)P_ * 64 * Vc];
__device__ float g_F[(long long)P_ * 64 * Vc];
__device__ float g_st1[P_ * 64 * 2];
__device__ float g_st2[P_ * 64 * 2];
__device__ float g_spS[P_ * NB2 * 64];
__device__ float g_spQ[P_ * NB2 * 64];
__device__ float g_CR[P_ * 64 * 512];
__device__ float g_X1p[16 * P_ * 512];
__device__ float g_X1[P_ * 512];
__device__ float g_X2[P_ * 256];

// ---------------- f32x2 helpers ----------------
__device__ __forceinline__ u64 ffma2(u64 a, u64 b, u64 c) {
    u64 d; asm("fma.rn.f32x2 %0, %1, %2, %3;" : "=l"(d) : "l"(a), "l"(b), "l"(c)); return d;
}
__device__ __forceinline__ u64 pk2(float x, float y) {
    u64 d; asm("mov.b64 %0, {%1, %2};" : "=l"(d) : "f"(x), "f"(y)); return d;
}
__device__ __forceinline__ float2 unpk2(u64 v) {
    float2 r; asm("mov.b64 {%0, %1}, %2;" : "=f"(r.x), "=f"(r.y) : "l"(v)); return r;
}

// ---------------- shared GEMM mainloop: one K=32 chunk ----------------
// Wsh: [32][64] slice (row-major, k fast dim outer), Xsh: [32][256] value-duplicated
__device__ __forceinline__ void mm_chunk(const float* Wsh, const float* Xsh,
                                         int tm, int tn, u64 acc[4][4]) {
#pragma unroll
    for (int k = 0; k < 32; k++) {
        ulonglong2 av0 = *(const ulonglong2*)(Wsh + k * 64 + tm * 8);
        ulonglong2 av1 = *(const ulonglong2*)(Wsh + k * 64 + tm * 8 + 4);
        ulonglong2 bv0 = *(const ulonglong2*)(Xsh + k * 256 + tn * 8);
        ulonglong2 bv1 = *(const ulonglong2*)(Xsh + k * 256 + tn * 8 + 4);
        u64 ap[4] = {av0.x, av0.y, av1.x, av1.y};   // M pairs (m,m+1)
        u64 bd[4] = {bv0.x, bv0.y, bv1.x, bv1.y};   // N dups  (n,n)
#pragma unroll
        for (int i = 0; i < 4; i++)
#pragma unroll
            for (int j = 0; j < 4; j++) acc[i][j] = ffma2(ap[i], bd[j], acc[i][j]);
    }
}

// stage W[64][128] (global, m-major) -> Ws[128][64] (k-major) in shared
__device__ __forceinline__ void stage_W(float* Ws, const float* w, int tid) {
    for (int i = tid; i < 8192; i += 256) { int m = i >> 7, k = i & 127; Ws[k * 64 + m] = w[i]; }
}

// ---------------- RPN: tiled conv 128->64 + fused heads ----------------
constexpr int RPN_SMEM = (8192 + 8192 + 64 * 132 + 64 * 22 + 24 + 64) * 4;
__global__ __launch_bounds__(256) void k_rpn2(
    const float* __restrict__ comb2,
    const float* __restrict__ w_rpn, const float* __restrict__ b_rpn,
    const float* __restrict__ w_rlog, const float* __restrict__ b_rlog,
    const float* __restrict__ w_rdel, const float* __restrict__ b_rdel,
    float* __restrict__ out)
{
    extern __shared__ float sm[];
    float* Ws = sm;                  // 8192
    float* Xs = sm + 8192;           // 8192
    float* Hs = sm + 16384;          // 64*132
    float* wc = Hs + 64 * 132;       // 64*22
    float* bc = wc + 64 * 22;        // 24
    float* sb = bc + 24;             // 64
    int tid = threadIdx.x;
    int vox0 = blockIdx.x * 128;

    stage_W(Ws, w_rpn, tid);
    for (int i = tid; i < 64 * 22; i += 256) {
        int o = i / 22, t = i - o * 22;
        float v = 0.f;
        if (t < 3) v = w_rlog[t * 64 + o];
        else if (t < 21) v = w_rdel[(t - 3) * 64 + o];
        wc[i] = v;
    }
    if (tid < 22) bc[tid] = (tid < 3) ? b_rlog[tid] : (tid < 21 ? b_rdel[tid - 3] : 0.f);
    if (tid < 64) sb[tid] = b_rpn[tid];
    __syncthreads();

    int tn = tid & 31, tm = tid >> 5;
    int col = tid & 127, rbase = tid >> 7;
    u64 acc[4][4];
#pragma unroll
    for (int i = 0; i < 4; i++) { int m = tm * 8 + 2 * i;
#pragma unroll
        for (int j = 0; j < 4; j++) acc[i][j] = pk2(sb[m], sb[m + 1]); }

#pragma unroll 1
    for (int kc = 0; kc < 4; kc++) {
        if (kc) __syncthreads();
#pragma unroll
        for (int it = 0; it < 16; it++) {
            int row = it * 2 + rbase;
            int c = kc * 32 + row;
            float val = __ldg(comb2 + (long long)c * NV2 + vox0 + col);
            *(float2*)&Xs[row * 256 + col * 2] = make_float2(val, val);
        }
        __syncthreads();
        mm_chunk(Ws + kc * 32 * 64, Xs, tm, tn, acc);
    }

    // store relu'd h into Hs [64][132]
#pragma unroll
    for (int i = 0; i < 4; i++) {
        int m = tm * 8 + 2 * i;
        float2 v0 = unpk2(acc[i][0]), v1 = unpk2(acc[i][1]), v2 = unpk2(acc[i][2]), v3 = unpk2(acc[i][3]);
        float4 lo = make_float4(fmaxf(v0.x, 0.f), fmaxf(v1.x, 0.f), fmaxf(v2.x, 0.f), fmaxf(v3.x, 0.f));
        float4 hi = make_float4(fmaxf(v0.y, 0.f), fmaxf(v1.y, 0.f), fmaxf(v2.y, 0.f), fmaxf(v3.y, 0.f));
        *(float4*)&Hs[m * 132 + tn * 4] = lo;
        *(float4*)&Hs[(m + 1) * 132 + tn * 4] = hi;
    }
    __syncthreads();

    // heads: 2 threads per voxel, 11 outputs each (t index into combined table)
    int vx = tid >> 1, half = tid & 1;
    int toff = half * 11;
    float a[11];
#pragma unroll
    for (int t = 0; t < 11; t++) a[t] = bc[toff + t];
    for (int o = 0; o < 64; o++) {
        float h = Hs[o * 132 + vx];
#pragma unroll
        for (int t = 0; t < 11; t++) a[t] = fmaf(wc[o * 22 + toff + t], h, a[t]);
    }
    long long vox = vox0 + vx;
#pragma unroll
    for (int t = 0; t < 11; t++) {
        int g = toff + t;
        if (g < 3) out[vox * 3 + g] = a[t];
        else if (g < 21) out[(long long)NV2 * 3 + vox * 18 + (g - 3)] = a[t];
    }
}

// ---------------- conv_low: up2 conv at 12^3 (tiled) ----------------
constexpr int CL_SMEM = (8192 + 8192 + 64) * 4;
__global__ __launch_bounds__(256) void k_conv_low2(
    const float* __restrict__ comb2, const int* __restrict__ props,
    const float* __restrict__ w_up2, const float* __restrict__ b_up2)
{
    extern __shared__ float sm[];
    float* Ws = sm; float* Xs = sm + 8192; float* sb = sm + 16384;
    int tid = threadIdx.x;
    int p = blockIdx.y, n0 = blockIdx.x * 128;

    stage_W(Ws, w_up2, tid);
    if (tid < 64) sb[tid] = b_up2[tid];

    int tn = tid & 31, tm = tid >> 5;
    int col = tid & 127, rbase = tid >> 7;
    int v = n0 + col; int vcl = (v < V4) ? v : 0;
    int z0 = props[p * 7 + 1] >> 2, y0 = props[p * 7 + 2] >> 2, x0 = props[p * 7 + 3] >> 2;
    int d = vcl / 144; int r = vcl - d * 144; int hh = r / 12; int ww = r - hh * 12;
    long long base = (long long)(z0 + d) * 4096 + (y0 + hh) * 64 + (x0 + ww);
    __syncthreads();

    u64 acc[4][4];
#pragma unroll
    for (int i = 0; i < 4; i++) { int m = tm * 8 + 2 * i;
#pragma unroll
        for (int j = 0; j < 4; j++) acc[i][j] = pk2(sb[m], sb[m + 1]); }

#pragma unroll 1
    for (int kc = 0; kc < 4; kc++) {
        if (kc) __syncthreads();
#pragma unroll
        for (int it = 0; it < 16; it++) {
            int row = it * 2 + rbase;
            int c = kc * 32 + row;
            float val = __ldg(comb2 + (long long)c * NV2 + base);
            *(float2*)&Xs[row * 256 + col * 2] = make_float2(val, val);
        }
        __syncthreads();
        mm_chunk(Ws + kc * 32 * 64, Xs, tm, tn, acc);
    }

    if (n0 + tn * 4 < V4) {
        float* Tb = g_T + (long long)(p * 64) * V4 + n0 + tn * 4;
#pragma unroll
        for (int i = 0; i < 4; i++) {
            int m = tm * 8 + 2 * i;
            float2 v0 = unpk2(acc[i][0]), v1 = unpk2(acc[i][1]), v2 = unpk2(acc[i][2]), v3 = unpk2(acc[i][3]);
            *(float4*)(Tb + (long long)m * V4) = make_float4(v0.x, v1.x, v2.x, v3.x);
            *(float4*)(Tb + (long long)(m + 1) * V4) = make_float4(v0.y, v1.y, v2.y, v3.y);
        }
    }
}

// ---------------- upsample 12->24 + U stats (unchanged from R1) ----------------
__device__ __forceinline__ void breduce2(float& s, float& ss) {
    __shared__ float bs[16], bss[16];
#pragma unroll
    for (int off = 16; off; off >>= 1) {
        s += __shfl_down_sync(0xffffffffu, s, off);
        ss += __shfl_down_sync(0xffffffffu, ss, off);
    }
    int wrp = threadIdx.x >> 5, ln = threadIdx.x & 31;
    int nw = blockDim.x >> 5;
    if (ln == 0) { bs[wrp] = s; bss[wrp] = ss; }
    __syncthreads();
    if (wrp == 0) {
        s = (ln < nw) ? bs[ln] : 0.f;
        ss = (ln < nw) ? bss[ln] : 0.f;
#pragma unroll
        for (int off = 16; off; off >>= 1) {
            s += __shfl_down_sync(0xffffffffu, s, off);
            ss += __shfl_down_sync(0xffffffffu, ss, off);
        }
    }
}

__global__ __launch_bounds__(256) void k_upsample()
{
    int c = blockIdx.x, p = blockIdx.y;
    __shared__ float t[V4];
    const float* tp = &g_T[(p * 64 + c) * V4];
    for (int i = threadIdx.x; i < V4; i += 256) t[i] = tp[i];
    __syncthreads();

    float s = 0.f, ss = 0.f;
    float* up = &g_U[((long long)(p * 64 + c)) * Vc];
    for (int v = threadIdx.x; v < Vc; v += 256) {
        int Dq = v / 576; int r = v - Dq * 576; int Hq = r / 24; int Wq = r - Hq * 24;
        int nd = Dq * 11; int ld = nd / 23; float fd = (float)(nd - ld * 23) * (1.0f / 23.0f); int hd = min(ld + 1, 11);
        int nh = Hq * 11; int lh = nh / 23; float fh = (float)(nh - lh * 23) * (1.0f / 23.0f); int hh = min(lh + 1, 11);
        int nwc = Wq * 11; int lw = nwc / 23; float fw = (float)(nwc - lw * 23) * (1.0f / 23.0f); int hw = min(lw + 1, 11);
        const float* t0 = &t[ld * 144]; const float* t1 = &t[hd * 144];
        float a00 = t0[lh * 12 + lw], a01 = t0[lh * 12 + hw], a10 = t0[hh * 12 + lw], a11 = t0[hh * 12 + hw];
        float b00 = t1[lh * 12 + lw], b01 = t1[lh * 12 + hw], b10 = t1[hh * 12 + lw], b11 = t1[hh * 12 + hw];
        float ww0 = 1.f - fw, wh0 = 1.f - fh, wd0 = 1.f - fd;
        float i00 = a00 * ww0 + a01 * fw, i01 = a10 * ww0 + a11 * fw;
        float i10 = b00 * ww0 + b01 * fw, i11 = b10 * ww0 + b11 * fw;
        float j0 = i00 * wh0 + i01 * fh, j1 = i10 * wh0 + i11 * fh;
        float val = j0 * wd0 + j1 * fd;
        up[v] = val;
        s += val; ss = fmaf(val, val, ss);
    }
    breduce2(s, ss);
    if (threadIdx.x == 0) { g_st1[(p * 64 + c) * 2] = s; g_st1[(p * 64 + c) * 2 + 1] = ss; }
}

// ---------------- back2: tiled GEMM + fused F-stats partials ----------------
constexpr int B2_SMEM = (8192 + 8192 + 192) * 4;
__global__ __launch_bounds__(256) void k_back2t(
    const float* __restrict__ out1, const int* __restrict__ props,
    const float* __restrict__ w_back2, const float* __restrict__ b_back2,
    const float* __restrict__ gam, const float* __restrict__ bet)
{
    extern __shared__ float sm[];
    float* Ws = sm; float* Xs = sm + 8192;
    float* sb = sm + 16384; float* sc = sb + 64; float* sh = sb + 128;
    int tid = threadIdx.x;
    int p = blockIdx.y, n0 = blockIdx.x * 128;

    stage_W(Ws, w_back2, tid);
    if (tid < 64) {
        sb[tid] = b_back2[tid];
        float s = g_st1[(p * 64 + tid) * 2], q = g_st1[(p * 64 + tid) * 2 + 1];
        float mean = s * (1.f / Vc);
        float var = q * (1.f / Vc) - mean * mean;
        float a = gam[tid] * rsqrtf(var + EPSN);
        sc[tid] = a; sh[tid] = bet[tid] - mean * a;
    }

    int tn = tid & 31, tm = tid >> 5;
    int col = tid & 127, rbase = tid >> 7;
    int v = n0 + col;
    int z0 = props[p * 7 + 1] >> 1, y0 = props[p * 7 + 2] >> 1, x0 = props[p * 7 + 3] >> 1;
    int d = v / 576; int r = v - d * 576; int hh = r / 24; int ww = r - hh * 24;
    long long o1base = ((long long)(z0 + d) * 128 + (y0 + hh)) * 128 + (x0 + ww);
    const float* Ub = g_U + ((long long)p * 64) * Vc + v;
    __syncthreads();

    u64 acc[4][4];
#pragma unroll
    for (int i = 0; i < 4; i++) { int m = tm * 8 + 2 * i;
#pragma unroll
        for (int j = 0; j < 4; j++) acc[i][j] = pk2(sb[m], sb[m + 1]); }

#pragma unroll 1
    for (int kc = 0; kc < 4; kc++) {
        if (kc) __syncthreads();
        if (kc < 2) {
#pragma unroll
            for (int it = 0; it < 16; it++) {
                int row = it * 2 + rbase;
                int c = kc * 32 + row;
                float uv = Ub[(long long)c * Vc];
                float val = fmaxf(fmaf(uv, sc[c], sh[c]), 0.f);
                *(float2*)&Xs[row * 256 + col * 2] = make_float2(val, val);
            }
        } else {
#pragma unroll
            for (int it = 0; it < 16; it++) {
                int row = it * 2 + rbase;
                int c = kc * 32 + row - 64;
                float val = __ldg(out1 + (long long)c * C1STRIDE + o1base);
                *(float2*)&Xs[row * 256 + col * 2] = make_float2(val, val);
            }
        }
        __syncthreads();
        mm_chunk(Ws + kc * 32 * 64, Xs, tm, tn, acc);
    }

    // epilogue: store F + warp-reduced per-channel partial stats
    float* Fb = g_F + ((long long)p * 64) * Vc + n0 + tn * 4;
    int pbase = (p * NB2 + blockIdx.x) * 64;
#pragma unroll
    for (int i = 0; i < 4; i++) {
        int m = tm * 8 + 2 * i;
        float2 v0 = unpk2(acc[i][0]), v1 = unpk2(acc[i][1]), v2 = unpk2(acc[i][2]), v3 = unpk2(acc[i][3]);
        float4 lo = make_float4(v0.x, v1.x, v2.x, v3.x);
        float4 hi = make_float4(v0.y, v1.y, v2.y, v3.y);
        *(float4*)(Fb + (long long)m * Vc) = lo;
        *(float4*)(Fb + (long long)(m + 1) * Vc) = hi;
        float sl = lo.x + lo.y + lo.z + lo.w;
        float ql = lo.x * lo.x + lo.y * lo.y + lo.z * lo.z + lo.w * lo.w;
        float sh2 = hi.x + hi.y + hi.z + hi.w;
        float qh = hi.x * hi.x + hi.y * hi.y + hi.z * hi.z + hi.w * hi.w;
#pragma unroll
        for (int off = 16; off; off >>= 1) {
            sl += __shfl_down_sync(0xffffffffu, sl, off);
            ql += __shfl_down_sync(0xffffffffu, ql, off);
            sh2 += __shfl_down_sync(0xffffffffu, sh2, off);
            qh += __shfl_down_sync(0xffffffffu, qh, off);
        }
        if (tn == 0) {
            g_spS[pbase + m] = sl;  g_spQ[pbase + m] = ql;
            g_spS[pbase + m + 1] = sh2; g_spQ[pbase + m + 1] = qh;
        }
    }
}

// ---------------- reduce F-stat partials ----------------
__global__ __launch_bounds__(64) void k_finstats()
{
    int p = blockIdx.x; int c = threadIdx.x;
    float S = 0.f, Q = 0.f;
    for (int b = 0; b < NB2; b++) {
        S += g_spS[(p * NB2 + b) * 64 + c];
        Q += g_spQ[(p * NB2 + b) * 64 + c];
    }
    g_st2[(p * 64 + c) * 2] = S;
    g_st2[(p * 64 + c) * 2 + 1] = Q;
}

// ---------------- normalize + relu + 3^3 maxpool ----------------
__global__ __launch_bounds__(512) void k_pool(
    const float* __restrict__ gam, const float* __restrict__ bet)
{
    int o = blockIdx.x, p = blockIdx.y;
    float s = g_st2[(p * 64 + o) * 2], q = g_st2[(p * 64 + o) * 2 + 1];
    float mean = s * (1.f / Vc);
    float var = q * (1.f / Vc) - mean * mean;
    float a = gam[o] * rsqrtf(var + EPSN);
    float b = bet[o] - mean * a;

    int j = threadIdx.x;
    int od = j >> 6; int r = j & 63; int oh = r >> 3; int ow = r & 7;
    const float* Fp = &g_F[((long long)(p * 64 + o)) * Vc];
    float m = -1e30f;
#pragma unroll
    for (int dz = 0; dz < 3; dz++)
#pragma unroll
        for (int dy = 0; dy < 3; dy++)
#pragma unroll
            for (int dx = 0; dx < 3; dx++) {
                float v = Fp[(od * 3 + dz) * 576 + (oh * 3 + dy) * 24 + (ow * 3 + dx)];
                m = fmaxf(m, fmaxf(fmaf(v, a, b), 0.f));
            }
    g_CR[(p * 64 + o) * 512 + j] = m;
}

// ---------------- fc1 GEMM (K-split) ----------------
__global__ __launch_bounds__(256) void k_fc1(const float* __restrict__ w_fc1)
{
    __shared__ float Ws[64 * 65];
    __shared__ float Xs[64 * 65];
    int tid = threadIdx.x;
    int m0 = blockIdx.x * 64;
    int kb = blockIdx.y;
    int tp = tid & 63, tm = tid >> 6;

    float acc[16];
#pragma unroll
    for (int i = 0; i < 16; i++) acc[i] = 0.f;

    for (int ch = 0; ch < 32; ch++) {
        int k0 = kb * 2048 + ch * 64;
#pragma unroll
        for (int it = 0; it < 16; it++) {
            int idx = tid + it * 256;
            int kk = idx & 63, row = idx >> 6;
            Ws[row * 65 + kk] = w_fc1[(long long)(m0 + row) * 32768 + k0 + kk];
            Xs[kk * 65 + row] = g_CR[row * 32768 + k0 + kk];
        }
        __syncthreads();
#pragma unroll 8
        for (int k = 0; k < 64; k++) {
            float xv = Xs[k * 65 + tp];
#pragma unroll
            for (int i = 0; i < 16; i++) acc[i] = fmaf(Ws[(tm * 16 + i) * 65 + k], xv, acc[i]);
        }
        __syncthreads();
    }
    float* outp = &g_X1p[((long long)kb * 64 + tp) * 512 + m0 + tm * 16];
#pragma unroll
    for (int i = 0; i < 16; i++) outp[i] = acc[i];
}

__global__ __launch_bounds__(512) void k_fc1red(const float* __restrict__ b_fc1)
{
    int p = blockIdx.x; int m = threadIdx.x;
    float s = b_fc1[m];
#pragma unroll
    for (int kb = 0; kb < 16; kb++) s += g_X1p[((long long)kb * 64 + p) * 512 + m];
    g_X1[p * 512 + m] = fmaxf(s, 0.f);
}

__global__ __launch_bounds__(256) void k_fc2(
    const float* __restrict__ w_fc2, const float* __restrict__ b_fc2)
{
    int p = blockIdx.x; int o = threadIdx.x;
    __shared__ float xs[512];
    for (int i = o; i < 512; i += 256) xs[i] = g_X1[p * 512 + i];
    __syncthreads();
    const float* wp = &w_fc2[o * 512];
    float s = b_fc2[o];
#pragma unroll 8
    for (int k = 0; k < 512; k++) s = fmaf(wp[k], xs[k], s);
    g_X2[p * 256 + o] = fmaxf(s, 0.f);
}

__global__ __launch_bounds__(32) void k_heads(
    const float* __restrict__ w_logit, const float* __restrict__ b_logit,
    const float* __restrict__ w_delta, const float* __restrict__ b_delta,
    float* __restrict__ out)
{
    int p = blockIdx.x; int ln = threadIdx.x;
    const float* x = &g_X2[p * 256];
    const long long offL = (long long)NV2 * 21;
    for (int t = 0; t < 14; t++) {
        const float* wp = (t < 2) ? &w_logit[t * 256] : &w_delta[(t - 2) * 256];
        float s = 0.f;
        for (int k = ln; k < 256; k += 32) s = fmaf(wp[k], x[k], s);
#pragma unroll
        for (int off = 16; off; off >>= 1) s += __shfl_down_sync(0xffffffffu, s, off);
        if (ln == 0) {
            if (t < 2) out[offL + p * 2 + t] = s + b_logit[t];
            else       out[offL + 128 + p * 12 + (t - 2)] = s + b_delta[t - 2];
        }
    }
}

// ---------------- launch ----------------
extern "C" void kernel_launch(void* const* d_in, const int* in_sizes, int n_in,
                              void* d_out, int out_size)
{
    const float* out1    = (const float*)d_in[0];
    const float* comb2   = (const float*)d_in[1];
    const int*   props   = (const int*)  d_in[2];
    const float* w_rpn   = (const float*)d_in[3];  const float* b_rpn   = (const float*)d_in[4];
    const float* w_rlog  = (const float*)d_in[5];  const float* b_rlog  = (const float*)d_in[6];
    const float* w_rdel  = (const float*)d_in[7];  const float* b_rdel  = (const float*)d_in[8];
    const float* w_up2   = (const float*)d_in[9];  const float* b_up2   = (const float*)d_in[10];
    const float* gu_up2  = (const float*)d_in[11]; const float* be_up2  = (const float*)d_in[12];
    const float* w_back2 = (const float*)d_in[13]; const float* b_back2 = (const float*)d_in[14];
    const float* gu_bk2  = (const float*)d_in[15]; const float* be_bk2  = (const float*)d_in[16];
    const float* w_fc1   = (const float*)d_in[17]; const float* b_fc1   = (const float*)d_in[18];
    const float* w_fc2   = (const float*)d_in[19]; const float* b_fc2   = (const float*)d_in[20];
    const float* w_logit = (const float*)d_in[21]; const float* b_logit = (const float*)d_in[22];
    const float* w_delta = (const float*)d_in[23]; const float* b_delta = (const float*)d_in[24];
    float* out = (float*)d_out;

    cudaFuncSetAttribute(k_rpn2, cudaFuncAttributeMaxDynamicSharedMemorySize, RPN_SMEM);
    cudaFuncSetAttribute(k_conv_low2, cudaFuncAttributeMaxDynamicSharedMemorySize, CL_SMEM);
    cudaFuncSetAttribute(k_back2t, cudaFuncAttributeMaxDynamicSharedMemorySize, B2_SMEM);

    k_rpn2<<<1024, 256, RPN_SMEM>>>(comb2, w_rpn, b_rpn, w_rlog, b_rlog, w_rdel, b_rdel, out);
    k_conv_low2<<<dim3(14, P_), 256, CL_SMEM>>>(comb2, props, w_up2, b_up2);
    k_upsample<<<dim3(64, P_), 256>>>();
    k_back2t<<<dim3(NB2, P_), 256, B2_SMEM>>>(out1, props, w_back2, b_back2, gu_up2, be_up2);
    k_finstats<<<P_, 64>>>();
    k_pool<<<dim3(64, P_), 512>>>(gu_bk2, be_bk2);
    k_fc1<<<dim3(8, 16), 256>>>(w_fc1);
    k_fc1red<<<P_, 512>>>(b_fc1);
    k_fc2<<<P_, 256>>>(w_fc2, b_fc2);
    k_heads<<<P_, 32>>>(w_logit, b_logit, w_delta, b_delta, out);
}

// round 3
// speedup vs baseline: 1.9005x; 1.6548x over previous
#include <cuda_runtime.h>
#include <cstdint>

// ---------------- problem constants ----------------
constexpr int P_   = 64;
constexpr int NV2  = 32 * 64 * 64;        // comb2 voxels / channel stride
constexpr int C1STRIDE = 64 * 128 * 128;  // out1 channel stride
constexpr int V4 = 1728;                  // 12^3
constexpr int Vc = 13824;                 // 24^3
constexpr int NB2 = 54;                   // back2 n-tiles per proposal (13824/256)
constexpr int WSS = 66;                   // Ws row stride (pad vs bank conflicts)
constexpr float EPSN = 1e-5f;

typedef unsigned long long u64;

// ---------------- scratch ----------------
__device__ float g_T[P_ * 64 * V4];
__device__ float g_U[(long long)P_ * 64 * Vc];
__device__ float g_F[(long long)P_ * 64 * Vc];
__device__ float g_st1[P_ * 64 * 2];
__device__ float g_st2[P_ * 64 * 2];
__device__ float g_spS[P_ * NB2 * 64];
__device__ float g_spQ[P_ * NB2 * 64];
__device__ float g_CR[P_ * 64 * 512];
__device__ float g_X1p[16 * P_ * 512];
__device__ float g_X1[P_ * 512];
__device__ float g_X2[P_ * 256];

// ---------------- f32x2 helpers ----------------
__device__ __forceinline__ u64 ffma2(u64 a, u64 b, u64 c) {
    u64 d; asm("fma.rn.f32x2 %0, %1, %2, %3;" : "=l"(d) : "l"(a), "l"(b), "l"(c)); return d;
}
__device__ __forceinline__ u64 pk2(float x, float y) {
    u64 d; asm("mov.b64 %0, {%1, %2};" : "=l"(d) : "f"(x), "f"(y)); return d;
}
__device__ __forceinline__ float2 unpk2(u64 v) {
    float2 r; asm("mov.b64 {%0, %1}, %2;" : "=f"(r.x), "=f"(r.y) : "l"(v)); return r;
}

// stage W[64][128] (global, m-major) -> Ws[128][WSS] (k-major, padded)
// coalesced global float4 reads; shared writes <=4-way conflicted (once per block)
__device__ __forceinline__ void stageW(float* Ws, const float* __restrict__ w, int tid) {
    int kg = (tid & 31) * 4;
    int mb = (tid >> 5) * 8;
#pragma unroll
    for (int mm = 0; mm < 8; mm++) {
        int m = mb + mm;
        float4 v = *(const float4*)(w + m * 128 + kg);
        Ws[(kg + 0) * WSS + m] = v.x;
        Ws[(kg + 1) * WSS + m] = v.y;
        Ws[(kg + 2) * WSS + m] = v.z;
        Ws[(kg + 3) * WSS + m] = v.w;
    }
}

// mainloop over one K=32 chunk.  W reads: 4x LDS.64 warp-broadcast.
// X reads: 2x LDS.128 conflict-free.  32 FFMA2 (=64 FMA) per thread per k.
__device__ __forceinline__ void mm32(const float* WsK, const float* Xs,
                                     int tm, int tn, u64 acc[4][8]) {
#pragma unroll 8
    for (int k = 0; k < 32; k++) {
        const float* wp = WsK + k * WSS + tm * 8;
        u64 a0 = *(const u64*)(wp);
        u64 a1 = *(const u64*)(wp + 2);
        u64 a2 = *(const u64*)(wp + 4);
        u64 a3 = *(const u64*)(wp + 6);
        float4 xl = *(const float4*)(Xs + k * 256 + tn * 4);
        float4 xh = *(const float4*)(Xs + k * 256 + 128 + tn * 4);
        u64 a[4] = {a0, a1, a2, a3};
        u64 b[8] = {pk2(xl.x, xl.x), pk2(xl.y, xl.y), pk2(xl.z, xl.z), pk2(xl.w, xl.w),
                    pk2(xh.x, xh.x), pk2(xh.y, xh.y), pk2(xh.z, xh.z), pk2(xh.w, xh.w)};
#pragma unroll
        for (int i = 0; i < 4; i++)
#pragma unroll
            for (int j = 0; j < 8; j++) acc[i][j] = ffma2(a[i], b[j], acc[i][j]);
    }
}

// ---------------- RPN: tiled conv 128->64 + fused heads ----------------
constexpr int RPN_SMEM = (128 * WSS + 8192 + 64 * 21 + 24 + 64) * 4;
__global__ __launch_bounds__(256, 2) void k_rpn2(
    const float* __restrict__ comb2,
    const float* __restrict__ w_rpn, const float* __restrict__ b_rpn,
    const float* __restrict__ w_rlog, const float* __restrict__ b_rlog,
    const float* __restrict__ w_rdel, const float* __restrict__ b_rdel,
    float* __restrict__ out)
{
    extern __shared__ float sm[];
    float* Ws = sm;                       // 128*WSS = 8448
    float* Xs = sm + 128 * WSS;           // 8192
    float* Hs = sm;                       // reuse [0,16384) after mainloop
    float* wc = sm + 128 * WSS + 8192;    // 64*21
    float* bc = wc + 64 * 21;             // 24
    float* sb = bc + 24;                  // 64
    int tid = threadIdx.x;
    int vox0 = blockIdx.x * 256;

    stageW(Ws, w_rpn, tid);
    for (int i = tid; i < 64 * 21; i += 256) {
        int o = i / 21, t = i - o * 21;
        wc[i] = (t < 3) ? w_rlog[t * 64 + o] : w_rdel[(t - 3) * 64 + o];
    }
    if (tid < 21) bc[tid] = (tid < 3) ? b_rlog[tid] : b_rdel[tid - 3];
    if (tid < 64) sb[tid] = b_rpn[tid];
    __syncthreads();

    int tn = tid & 31, tm = tid >> 5;
    int c4 = tid & 63, rg = tid >> 6;
    u64 acc[4][8];
#pragma unroll
    for (int i = 0; i < 4; i++) { int m = tm * 8 + 2 * i;
#pragma unroll
        for (int j = 0; j < 8; j++) acc[i][j] = pk2(sb[m], sb[m + 1]); }

#pragma unroll 1
    for (int kc = 0; kc < 4; kc++) {
        if (kc) __syncthreads();
#pragma unroll
        for (int rr = 0; rr < 8; rr++) {
            int row = rg * 8 + rr;
            int c = kc * 32 + row;
            float4 v = *(const float4*)(comb2 + (long long)c * NV2 + vox0 + c4 * 4);
            *(float4*)&Xs[row * 256 + c4 * 4] = v;
        }
        __syncthreads();
        mm32(Ws + kc * 32 * WSS, Xs, tm, tn, acc);
    }
    __syncthreads();   // before overwriting Ws/Xs region with Hs

    // store relu'd h into Hs[64][256]
#pragma unroll
    for (int i = 0; i < 4; i++) {
        int m = tm * 8 + 2 * i;
#pragma unroll
        for (int h = 0; h < 2; h++) {
            float2 v0 = unpk2(acc[i][h * 4 + 0]), v1 = unpk2(acc[i][h * 4 + 1]);
            float2 v2 = unpk2(acc[i][h * 4 + 2]), v3 = unpk2(acc[i][h * 4 + 3]);
            *(float4*)&Hs[m * 256 + h * 128 + tn * 4] =
                make_float4(fmaxf(v0.x, 0.f), fmaxf(v1.x, 0.f), fmaxf(v2.x, 0.f), fmaxf(v3.x, 0.f));
            *(float4*)&Hs[(m + 1) * 256 + h * 128 + tn * 4] =
                make_float4(fmaxf(v0.y, 0.f), fmaxf(v1.y, 0.f), fmaxf(v2.y, 0.f), fmaxf(v3.y, 0.f));
        }
    }
    __syncthreads();

    // heads: 1 thread per voxel, 21 outputs
    int vx = tid;
    float a[21];
#pragma unroll
    for (int t = 0; t < 21; t++) a[t] = bc[t];
    for (int o = 0; o < 64; o++) {
        float h = Hs[o * 256 + vx];
#pragma unroll
        for (int t = 0; t < 21; t++) a[t] = fmaf(wc[o * 21 + t], h, a[t]);
    }
    long long vox = vox0 + vx;
#pragma unroll
    for (int t = 0; t < 3; t++) out[vox * 3 + t] = a[t];
#pragma unroll
    for (int t = 0; t < 18; t++) out[(long long)NV2 * 3 + vox * 18 + t] = a[3 + t];
}

// ---------------- conv_low: up2 conv at 12^3 ----------------
constexpr int CL_SMEM = (128 * WSS + 8192 + 64) * 4;
__global__ __launch_bounds__(256, 2) void k_conv_low2(
    const float* __restrict__ comb2, const int* __restrict__ props,
    const float* __restrict__ w_up2, const float* __restrict__ b_up2)
{
    extern __shared__ float sm[];
    float* Ws = sm; float* Xs = sm + 128 * WSS; float* sb = Xs + 8192;
    int tid = threadIdx.x;
    int p = blockIdx.y, n0 = blockIdx.x * 256;

    stageW(Ws, w_up2, tid);
    if (tid < 64) sb[tid] = b_up2[tid];

    int tn = tid & 31, tm = tid >> 5;
    int c4 = tid & 63, rg = tid >> 6;
    int v4 = n0 + c4 * 4; if (v4 > V4 - 4) v4 = V4 - 4;
    int z0 = props[p * 7 + 1] >> 2, y0 = props[p * 7 + 2] >> 2, x0 = props[p * 7 + 3] >> 2;
    int d = v4 / 144; int r = v4 - d * 144; int hh = r / 12; int ww = r - hh * 12;
    long long base = (long long)(z0 + d) * 4096 + (y0 + hh) * 64 + (x0 + ww);
    __syncthreads();

    u64 acc[4][8];
#pragma unroll
    for (int i = 0; i < 4; i++) { int m = tm * 8 + 2 * i;
#pragma unroll
        for (int j = 0; j < 8; j++) acc[i][j] = pk2(sb[m], sb[m + 1]); }

#pragma unroll 1
    for (int kc = 0; kc < 4; kc++) {
        if (kc) __syncthreads();
#pragma unroll
        for (int rr = 0; rr < 8; rr++) {
            int row = rg * 8 + rr;
            int c = kc * 32 + row;
            const float* gp = comb2 + (long long)c * NV2 + base;
            *(float4*)&Xs[row * 256 + c4 * 4] =
                make_float4(__ldg(gp), __ldg(gp + 1), __ldg(gp + 2), __ldg(gp + 3));
        }
        __syncthreads();
        mm32(Ws + kc * 32 * WSS, Xs, tm, tn, acc);
    }

    float* Tb = g_T + (long long)(p * 64) * V4 + n0 + tn * 4;
#pragma unroll
    for (int i = 0; i < 4; i++) {
        int m = tm * 8 + 2 * i;
#pragma unroll
        for (int h = 0; h < 2; h++) {
            int n = n0 + h * 128 + tn * 4;
            if (n < V4) {
                float2 v0 = unpk2(acc[i][h * 4 + 0]), v1 = unpk2(acc[i][h * 4 + 1]);
                float2 v2 = unpk2(acc[i][h * 4 + 2]), v3 = unpk2(acc[i][h * 4 + 3]);
                *(float4*)(Tb + (long long)m * V4 + h * 128) = make_float4(v0.x, v1.x, v2.x, v3.x);
                *(float4*)(Tb + (long long)(m + 1) * V4 + h * 128) = make_float4(v0.y, v1.y, v2.y, v3.y);
            }
        }
    }
}

// ---------------- upsample 12->24 + U stats ----------------
__device__ __forceinline__ void breduce2(float& s, float& ss) {
    __shared__ float bs[16], bss[16];
#pragma unroll
    for (int off = 16; off; off >>= 1) {
        s += __shfl_down_sync(0xffffffffu, s, off);
        ss += __shfl_down_sync(0xffffffffu, ss, off);
    }
    int wrp = threadIdx.x >> 5, ln = threadIdx.x & 31;
    int nw = blockDim.x >> 5;
    if (ln == 0) { bs[wrp] = s; bss[wrp] = ss; }
    __syncthreads();
    if (wrp == 0) {
        s = (ln < nw) ? bs[ln] : 0.f;
        ss = (ln < nw) ? bss[ln] : 0.f;
#pragma unroll
        for (int off = 16; off; off >>= 1) {
            s += __shfl_down_sync(0xffffffffu, s, off);
            ss += __shfl_down_sync(0xffffffffu, ss, off);
        }
    }
}

__global__ __launch_bounds__(256) void k_upsample()
{
    int c = blockIdx.x, p = blockIdx.y;
    __shared__ float t[V4];
    const float* tp = &g_T[(p * 64 + c) * V4];
    for (int i = threadIdx.x; i < V4; i += 256) t[i] = tp[i];
    __syncthreads();

    float s = 0.f, ss = 0.f;
    float* up = &g_U[((long long)(p * 64 + c)) * Vc];
    for (int v = threadIdx.x; v < Vc; v += 256) {
        int Dq = v / 576; int r = v - Dq * 576; int Hq = r / 24; int Wq = r - Hq * 24;
        int nd = Dq * 11; int ld = nd / 23; float fd = (float)(nd - ld * 23) * (1.0f / 23.0f); int hd = min(ld + 1, 11);
        int nh = Hq * 11; int lh = nh / 23; float fh = (float)(nh - lh * 23) * (1.0f / 23.0f); int hh = min(lh + 1, 11);
        int nwc = Wq * 11; int lw = nwc / 23; float fw = (float)(nwc - lw * 23) * (1.0f / 23.0f); int hw = min(lw + 1, 11);
        const float* t0 = &t[ld * 144]; const float* t1 = &t[hd * 144];
        float a00 = t0[lh * 12 + lw], a01 = t0[lh * 12 + hw], a10 = t0[hh * 12 + lw], a11 = t0[hh * 12 + hw];
        float b00 = t1[lh * 12 + lw], b01 = t1[lh * 12 + hw], b10 = t1[hh * 12 + lw], b11 = t1[hh * 12 + hw];
        float ww0 = 1.f - fw, wh0 = 1.f - fh, wd0 = 1.f - fd;
        float i00 = a00 * ww0 + a01 * fw, i01 = a10 * ww0 + a11 * fw;
        float i10 = b00 * ww0 + b01 * fw, i11 = b10 * ww0 + b11 * fw;
        float j0 = i00 * wh0 + i01 * fh, j1 = i10 * wh0 + i11 * fh;
        float val = j0 * wd0 + j1 * fd;
        up[v] = val;
        s += val; ss = fmaf(val, val, ss);
    }
    breduce2(s, ss);
    if (threadIdx.x == 0) { g_st1[(p * 64 + c) * 2] = s; g_st1[(p * 64 + c) * 2 + 1] = ss; }
}

// ---------------- back2: tiled GEMM + fused F-stats partials ----------------
constexpr int B2_SMEM = (128 * WSS + 8192 + 192) * 4;
__global__ __launch_bounds__(256, 2) void k_back2t(
    const float* __restrict__ out1, const int* __restrict__ props,
    const float* __restrict__ w_back2, const float* __restrict__ b_back2,
    const float* __restrict__ gam, const float* __restrict__ bet)
{
    extern __shared__ float sm[];
    float* Ws = sm; float* Xs = sm + 128 * WSS;
    float* sb = Xs + 8192; float* sc = sb + 64; float* sh = sb + 128;
    int tid = threadIdx.x;
    int p = blockIdx.y, n0 = blockIdx.x * 256;

    stageW(Ws, w_back2, tid);
    if (tid < 64) {
        sb[tid] = b_back2[tid];
        float s = g_st1[(p * 64 + tid) * 2], q = g_st1[(p * 64 + tid) * 2 + 1];
        float mean = s * (1.f / Vc);
        float var = q * (1.f / Vc) - mean * mean;
        float a = gam[tid] * rsqrtf(var + EPSN);
        sc[tid] = a; sh[tid] = bet[tid] - mean * a;
    }

    int tn = tid & 31, tm = tid >> 5;
    int c4 = tid & 63, rg = tid >> 6;
    int v4 = n0 + c4 * 4;
    int z0 = props[p * 7 + 1] >> 1, y0 = props[p * 7 + 2] >> 1, x0 = props[p * 7 + 3] >> 1;
    int d = v4 / 576; int r = v4 - d * 576; int hh = r / 24; int ww = r - hh * 24;
    long long o1b = ((long long)(z0 + d) * 128 + (y0 + hh)) * 128 + (x0 + ww);
    const float* Ub = g_U + ((long long)p * 64) * Vc + v4;
    __syncthreads();

    u64 acc[4][8];
#pragma unroll
    for (int i = 0; i < 4; i++) { int m = tm * 8 + 2 * i;
#pragma unroll
        for (int j = 0; j < 8; j++) acc[i][j] = pk2(sb[m], sb[m + 1]); }

#pragma unroll 1
    for (int kc = 0; kc < 4; kc++) {
        if (kc) __syncthreads();
        if (kc < 2) {
#pragma unroll
            for (int rr = 0; rr < 8; rr++) {
                int row = rg * 8 + rr;
                int c = kc * 32 + row;
                float4 u = *(const float4*)(Ub + (long long)c * Vc);
                float a = sc[c], b = sh[c];
                *(float4*)&Xs[row * 256 + c4 * 4] =
                    make_float4(fmaxf(fmaf(u.x, a, b), 0.f), fmaxf(fmaf(u.y, a, b), 0.f),
                                fmaxf(fmaf(u.z, a, b), 0.f), fmaxf(fmaf(u.w, a, b), 0.f));
            }
        } else {
#pragma unroll
            for (int rr = 0; rr < 8; rr++) {
                int row = rg * 8 + rr;
                int c = kc * 32 + row - 64;
                const float* gp = out1 + (long long)c * C1STRIDE + o1b;
                float2 e0 = *(const float2*)(gp);
                float2 e1 = *(const float2*)(gp + 2);
                *(float4*)&Xs[row * 256 + c4 * 4] = make_float4(e0.x, e0.y, e1.x, e1.y);
            }
        }
        __syncthreads();
        mm32(Ws + kc * 32 * WSS, Xs, tm, tn, acc);
    }

    // epilogue: store F + warp-reduced per-channel partial stats
    float* Fb = g_F + ((long long)p * 64) * Vc + n0 + tn * 4;
    int pbase = (p * NB2 + blockIdx.x) * 64;
#pragma unroll
    for (int i = 0; i < 4; i++) {
        int m = tm * 8 + 2 * i;
        float sl = 0.f, ql = 0.f, sh2 = 0.f, qh = 0.f;
#pragma unroll
        for (int h = 0; h < 2; h++) {
            float2 v0 = unpk2(acc[i][h * 4 + 0]), v1 = unpk2(acc[i][h * 4 + 1]);
            float2 v2 = unpk2(acc[i][h * 4 + 2]), v3 = unpk2(acc[i][h * 4 + 3]);
            float4 lo = make_float4(v0.x, v1.x, v2.x, v3.x);
            float4 hi = make_float4(v0.y, v1.y, v2.y, v3.y);
            *(float4*)(Fb + (long long)m * Vc + h * 128) = lo;
            *(float4*)(Fb + (long long)(m + 1) * Vc + h * 128) = hi;
            sl += lo.x + lo.y + lo.z + lo.w;
            ql += lo.x * lo.x + lo.y * lo.y + lo.z * lo.z + lo.w * lo.w;
            sh2 += hi.x + hi.y + hi.z + hi.w;
            qh += hi.x * hi.x + hi.y * hi.y + hi.z * hi.z + hi.w * hi.w;
        }
#pragma unroll
        for (int off = 16; off; off >>= 1) {
            sl += __shfl_down_sync(0xffffffffu, sl, off);
            ql += __shfl_down_sync(0xffffffffu, ql, off);
            sh2 += __shfl_down_sync(0xffffffffu, sh2, off);
            qh += __shfl_down_sync(0xffffffffu, qh, off);
        }
        if (tn == 0) {
            g_spS[pbase + m] = sl;  g_spQ[pbase + m] = ql;
            g_spS[pbase + m + 1] = sh2; g_spQ[pbase + m + 1] = qh;
        }
    }
}

// ---------------- reduce F-stat partials ----------------
__global__ __launch_bounds__(64) void k_finstats()
{
    int p = blockIdx.x; int c = threadIdx.x;
    float S = 0.f, Q = 0.f;
    for (int b = 0; b < NB2; b++) {
        S += g_spS[(p * NB2 + b) * 64 + c];
        Q += g_spQ[(p * NB2 + b) * 64 + c];
    }
    g_st2[(p * 64 + c) * 2] = S;
    g_st2[(p * 64 + c) * 2 + 1] = Q;
}

// ---------------- normalize + relu + 3^3 maxpool ----------------
__global__ __launch_bounds__(512) void k_pool(
    const float* __restrict__ gam, const float* __restrict__ bet)
{
    int o = blockIdx.x, p = blockIdx.y;
    float s = g_st2[(p * 64 + o) * 2], q = g_st2[(p * 64 + o) * 2 + 1];
    float mean = s * (1.f / Vc);
    float var = q * (1.f / Vc) - mean * mean;
    float a = gam[o] * rsqrtf(var + EPSN);
    float b = bet[o] - mean * a;

    int j = threadIdx.x;
    int od = j >> 6; int r = j & 63; int oh = r >> 3; int ow = r & 7;
    const float* Fp = &g_F[((long long)(p * 64 + o)) * Vc];
    float m = -1e30f;
#pragma unroll
    for (int dz = 0; dz < 3; dz++)
#pragma unroll
        for (int dy = 0; dy < 3; dy++)
#pragma unroll
            for (int dx = 0; dx < 3; dx++) {
                float v = Fp[(od * 3 + dz) * 576 + (oh * 3 + dy) * 24 + (ow * 3 + dx)];
                m = fmaxf(m, fmaxf(fmaf(v, a, b), 0.f));
            }
    g_CR[(p * 64 + o) * 512 + j] = m;
}

// ---------------- fc1 GEMM (K-split) ----------------
__global__ __launch_bounds__(256) void k_fc1(const float* __restrict__ w_fc1)
{
    __shared__ float Ws[64 * 65];
    __shared__ float Xs[64 * 65];
    int tid = threadIdx.x;
    int m0 = blockIdx.x * 64;
    int kb = blockIdx.y;
    int tp = tid & 63, tm = tid >> 6;

    float acc[16];
#pragma unroll
    for (int i = 0; i < 16; i++) acc[i] = 0.f;

    for (int ch = 0; ch < 32; ch++) {
        int k0 = kb * 2048 + ch * 64;
#pragma unroll
        for (int it = 0; it < 16; it++) {
            int idx = tid + it * 256;
            int kk = idx & 63, row = idx >> 6;
            Ws[row * 65 + kk] = w_fc1[(long long)(m0 + row) * 32768 + k0 + kk];
            Xs[kk * 65 + row] = g_CR[row * 32768 + k0 + kk];
        }
        __syncthreads();
#pragma unroll 8
        for (int k = 0; k < 64; k++) {
            float xv = Xs[k * 65 + tp];
#pragma unroll
            for (int i = 0; i < 16; i++) acc[i] = fmaf(Ws[(tm * 16 + i) * 65 + k], xv, acc[i]);
        }
        __syncthreads();
    }
    float* outp = &g_X1p[((long long)kb * 64 + tp) * 512 + m0 + tm * 16];
#pragma unroll
    for (int i = 0; i < 16; i++) outp[i] = acc[i];
}

__global__ __launch_bounds__(512) void k_fc1red(const float* __restrict__ b_fc1)
{
    int p = blockIdx.x; int m = threadIdx.x;
    float s = b_fc1[m];
#pragma unroll
    for (int kb = 0; kb < 16; kb++) s += g_X1p[((long long)kb * 64 + p) * 512 + m];
    g_X1[p * 512 + m] = fmaxf(s, 0.f);
}

__global__ __launch_bounds__(256) void k_fc2(
    const float* __restrict__ w_fc2, const float* __restrict__ b_fc2)
{
    int p = blockIdx.x; int o = threadIdx.x;
    __shared__ float xs[512];
    for (int i = o; i < 512; i += 256) xs[i] = g_X1[p * 512 + i];
    __syncthreads();
    const float* wp = &w_fc2[o * 512];
    float s = b_fc2[o];
#pragma unroll 8
    for (int k = 0; k < 512; k++) s = fmaf(wp[k], xs[k], s);
    g_X2[p * 256 + o] = fmaxf(s, 0.f);
}

__global__ __launch_bounds__(32) void k_heads(
    const float* __restrict__ w_logit, const float* __restrict__ b_logit,
    const float* __restrict__ w_delta, const float* __restrict__ b_delta,
    float* __restrict__ out)
{
    int p = blockIdx.x; int ln = threadIdx.x;
    const float* x = &g_X2[p * 256];
    const long long offL = (long long)NV2 * 21;
    for (int t = 0; t < 14; t++) {
        const float* wp = (t < 2) ? &w_logit[t * 256] : &w_delta[(t - 2) * 256];
        float s = 0.f;
        for (int k = ln; k < 256; k += 32) s = fmaf(wp[k], x[k], s);
#pragma unroll
        for (int off = 16; off; off >>= 1) s += __shfl_down_sync(0xffffffffu, s, off);
        if (ln == 0) {
            if (t < 2) out[offL + p * 2 + t] = s + b_logit[t];
            else       out[offL + 128 + p * 12 + (t - 2)] = s + b_delta[t - 2];
        }
    }
}

// ---------------- launch ----------------
extern "C" void kernel_launch(void* const* d_in, const int* in_sizes, int n_in,
                              void* d_out, int out_size)
{
    const float* out1    = (const float*)d_in[0];
    const float* comb2   = (const float*)d_in[1];
    const int*   props   = (const int*)  d_in[2];
    const float* w_rpn   = (const float*)d_in[3];  const float* b_rpn   = (const float*)d_in[4];
    const float* w_rlog  = (const float*)d_in[5];  const float* b_rlog  = (const float*)d_in[6];
    const float* w_rdel  = (const float*)d_in[7];  const float* b_rdel  = (const float*)d_in[8];
    const float* w_up2   = (const float*)d_in[9];  const float* b_up2   = (const float*)d_in[10];
    const float* gu_up2  = (const float*)d_in[11]; const float* be_up2  = (const float*)d_in[12];
    const float* w_back2 = (const float*)d_in[13]; const float* b_back2 = (const float*)d_in[14];
    const float* gu_bk2  = (const float*)d_in[15]; const float* be_bk2  = (const float*)d_in[16];
    const float* w_fc1   = (const float*)d_in[17]; const float* b_fc1   = (const float*)d_in[18];
    const float* w_fc2   = (const float*)d_in[19]; const float* b_fc2   = (const float*)d_in[20];
    const float* w_logit = (const float*)d_in[21]; const float* b_logit = (const float*)d_in[22];
    const float* w_delta = (const float*)d_in[23]; const float* b_delta = (const float*)d_in[24];
    float* out = (float*)d_out;

    cudaFuncSetAttribute(k_rpn2, cudaFuncAttributeMaxDynamicSharedMemorySize, RPN_SMEM);
    cudaFuncSetAttribute(k_conv_low2, cudaFuncAttributeMaxDynamicSharedMemorySize, CL_SMEM);
    cudaFuncSetAttribute(k_back2t, cudaFuncAttributeMaxDynamicSharedMemorySize, B2_SMEM);

    k_rpn2<<<512, 256, RPN_SMEM>>>(comb2, w_rpn, b_rpn, w_rlog, b_rlog, w_rdel, b_rdel, out);
    k_conv_low2<<<dim3(7, P_), 256, CL_SMEM>>>(comb2, props, w_up2, b_up2);
    k_upsample<<<dim3(64, P_), 256>>>();
    k_back2t<<<dim3(NB2, P_), 256, B2_SMEM>>>(out1, props, w_back2, b_back2, gu_up2, be_up2);
    k_finstats<<<P_, 64>>>();
    k_pool<<<dim3(64, P_), 512>>>(gu_bk2, be_bk2);
    k_fc1<<<dim3(8, 16), 256>>>(w_fc1);
    k_fc1red<<<P_, 512>>>(b_fc1);
    k_fc2<<<P_, 256>>>(w_fc2, b_fc2);
    k_heads<<<P_, 32>>>(w_logit, b_logit, w_delta, b_delta, out);
}

// round 4
// speedup vs baseline: 1.9280x; 1.0145x over previous
#include <cuda_runtime.h>
#include <cstdint>

// ---------------- problem constants ----------------
constexpr int P_   = 64;
constexpr int NV2  = 32 * 64 * 64;        // comb2 voxels / channel stride
constexpr int C1STRIDE = 64 * 128 * 128;  // out1 channel stride
constexpr int V4 = 1728;                  // 12^3
constexpr int Vc = 13824;                 // 24^3
constexpr int NB2 = 54;                   // back2 n-tiles per proposal (13824/256)
constexpr int WSS = 66;                   // Ws row stride (pad vs bank conflicts)
constexpr float EPSN = 1e-5f;

typedef unsigned long long u64;

// ---------------- scratch ----------------
__device__ float g_T[P_ * 64 * V4];
__device__ float g_U[(long long)P_ * 64 * Vc];
__device__ float g_F[(long long)P_ * 64 * Vc];
__device__ float g_st1[P_ * 64 * 2];
__device__ float g_spS[P_ * NB2 * 64];
__device__ float g_spQ[P_ * NB2 * 64];
__device__ float g_CR[P_ * 64 * 512];
__device__ float g_X1p[16 * P_ * 512];
__device__ float g_X1[P_ * 512];

// ---------------- f32x2 helpers ----------------
__device__ __forceinline__ u64 ffma2(u64 a, u64 b, u64 c) {
    u64 d; asm("fma.rn.f32x2 %0, %1, %2, %3;" : "=l"(d) : "l"(a), "l"(b), "l"(c)); return d;
}
__device__ __forceinline__ u64 pk2(float x, float y) {
    u64 d; asm("mov.b64 %0, {%1, %2};" : "=l"(d) : "f"(x), "f"(y)); return d;
}
__device__ __forceinline__ float2 unpk2(u64 v) {
    float2 r; asm("mov.b64 {%0, %1}, %2;" : "=f"(r.x), "=f"(r.y) : "l"(v)); return r;
}

// stage W[64][128] (global, m-major) -> Ws[128][WSS] (k-major, padded)
__device__ __forceinline__ void stageW(float* Ws, const float* __restrict__ w, int tid) {
    int kg = (tid & 31) * 4;
    int mb = (tid >> 5) * 8;
#pragma unroll
    for (int mm = 0; mm < 8; mm++) {
        int m = mb + mm;
        float4 v = *(const float4*)(w + m * 128 + kg);
        Ws[(kg + 0) * WSS + m] = v.x;
        Ws[(kg + 1) * WSS + m] = v.y;
        Ws[(kg + 2) * WSS + m] = v.z;
        Ws[(kg + 3) * WSS + m] = v.w;
    }
}

// mainloop over one K=32 chunk
__device__ __forceinline__ void mm32(const float* WsK, const float* Xs,
                                     int tm, int tn, u64 acc[4][8]) {
#pragma unroll 8
    for (int k = 0; k < 32; k++) {
        const float* wp = WsK + k * WSS + tm * 8;
        u64 a0 = *(const u64*)(wp);
        u64 a1 = *(const u64*)(wp + 2);
        u64 a2 = *(const u64*)(wp + 4);
        u64 a3 = *(const u64*)(wp + 6);
        float4 xl = *(const float4*)(Xs + k * 256 + tn * 4);
        float4 xh = *(const float4*)(Xs + k * 256 + 128 + tn * 4);
        u64 a[4] = {a0, a1, a2, a3};
        u64 b[8] = {pk2(xl.x, xl.x), pk2(xl.y, xl.y), pk2(xl.z, xl.z), pk2(xl.w, xl.w),
                    pk2(xh.x, xh.x), pk2(xh.y, xh.y), pk2(xh.z, xh.z), pk2(xh.w, xh.w)};
#pragma unroll
        for (int i = 0; i < 4; i++)
#pragma unroll
            for (int j = 0; j < 8; j++) acc[i][j] = ffma2(a[i], b[j], acc[i][j]);
    }
}

// ---------------- RPN: tiled conv 128->64 + fused heads (double-buffered) ----------------
constexpr int RPN_FLOATS = 8448 + 8192 + 8192 + 1344 + 24 + 64;
constexpr int RPN_SMEM = RPN_FLOATS * 4;
__global__ __launch_bounds__(256, 2) void k_rpn2(
    const float* __restrict__ comb2,
    const float* __restrict__ w_rpn, const float* __restrict__ b_rpn,
    const float* __restrict__ w_rlog, const float* __restrict__ b_rlog,
    const float* __restrict__ w_rdel, const float* __restrict__ b_rdel,
    float* __restrict__ out)
{
    extern __shared__ float sm[];
    float* Ws  = sm;                 // [0, 8448)
    float* Xs0 = sm + 8448;          // [8448, 16640)
    float* Xs1 = sm + 16640;         // [16640, 24832)
    float* wc  = sm + 24832;         // 1344
    float* bc  = wc + 1344;          // 24
    float* sb  = bc + 24;            // 64
    float* Hs  = sm;                 // reuse [0,16384) after mainloop
    int tid = threadIdx.x;
    int vox0 = blockIdx.x * 256;

    stageW(Ws, w_rpn, tid);
    for (int i = tid; i < 64 * 21; i += 256) {
        int o = i / 21, t = i - o * 21;
        wc[i] = (t < 3) ? w_rlog[t * 64 + o] : w_rdel[(t - 3) * 64 + o];
    }
    if (tid < 21) bc[tid] = (tid < 3) ? b_rlog[tid] : b_rdel[tid - 3];
    if (tid < 64) sb[tid] = b_rpn[tid];

    int tn = tid & 31, tm = tid >> 5;
    int c4 = tid & 63, rg = tid >> 6;
    u64 acc[4][8];

    // stage chunk 0
#pragma unroll
    for (int rr = 0; rr < 8; rr++) {
        int row = rg * 8 + rr;
        float4 v = *(const float4*)(comb2 + (long long)row * NV2 + vox0 + c4 * 4);
        *(float4*)&Xs0[row * 256 + c4 * 4] = v;
    }
    __syncthreads();

#pragma unroll
    for (int i = 0; i < 4; i++) { int m = tm * 8 + 2 * i;
#pragma unroll
        for (int j = 0; j < 8; j++) acc[i][j] = pk2(sb[m], sb[m + 1]); }

#pragma unroll 1
    for (int kc = 0; kc < 4; kc++) {
        float* Xc = (kc & 1) ? Xs1 : Xs0;
        float* Xn = (kc & 1) ? Xs0 : Xs1;
        if (kc < 3) {
#pragma unroll
            for (int rr = 0; rr < 8; rr++) {
                int row = rg * 8 + rr;
                int c = (kc + 1) * 32 + row;
                float4 v = *(const float4*)(comb2 + (long long)c * NV2 + vox0 + c4 * 4);
                *(float4*)&Xn[row * 256 + c4 * 4] = v;
            }
        }
        mm32(Ws + kc * 32 * WSS, Xc, tm, tn, acc);
        __syncthreads();
    }

    // store relu'd h into Hs[64][256]
#pragma unroll
    for (int i = 0; i < 4; i++) {
        int m = tm * 8 + 2 * i;
#pragma unroll
        for (int h = 0; h < 2; h++) {
            float2 v0 = unpk2(acc[i][h * 4 + 0]), v1 = unpk2(acc[i][h * 4 + 1]);
            float2 v2 = unpk2(acc[i][h * 4 + 2]), v3 = unpk2(acc[i][h * 4 + 3]);
            *(float4*)&Hs[m * 256 + h * 128 + tn * 4] =
                make_float4(fmaxf(v0.x, 0.f), fmaxf(v1.x, 0.f), fmaxf(v2.x, 0.f), fmaxf(v3.x, 0.f));
            *(float4*)&Hs[(m + 1) * 256 + h * 128 + tn * 4] =
                make_float4(fmaxf(v0.y, 0.f), fmaxf(v1.y, 0.f), fmaxf(v2.y, 0.f), fmaxf(v3.y, 0.f));
        }
    }
    __syncthreads();

    int vx = tid;
    float a[21];
#pragma unroll
    for (int t = 0; t < 21; t++) a[t] = bc[t];
    for (int o = 0; o < 64; o++) {
        float h = Hs[o * 256 + vx];
#pragma unroll
        for (int t = 0; t < 21; t++) a[t] = fmaf(wc[o * 21 + t], h, a[t]);
    }
    long long vox = vox0 + vx;
#pragma unroll
    for (int t = 0; t < 3; t++) out[vox * 3 + t] = a[t];
#pragma unroll
    for (int t = 0; t < 18; t++) out[(long long)NV2 * 3 + vox * 18 + t] = a[3 + t];
}

// ---------------- conv_low: up2 conv at 12^3 (double-buffered) ----------------
constexpr int CL_FLOATS = 8448 + 8192 + 8192 + 64;
constexpr int CL_SMEM = CL_FLOATS * 4;
__global__ __launch_bounds__(256, 2) void k_conv_low2(
    const float* __restrict__ comb2, const int* __restrict__ props,
    const float* __restrict__ w_up2, const float* __restrict__ b_up2)
{
    extern __shared__ float sm[];
    float* Ws = sm; float* Xs0 = sm + 8448; float* Xs1 = sm + 16640;
    float* sb = sm + 24832;
    int tid = threadIdx.x;
    int p = blockIdx.y, n0 = blockIdx.x * 256;

    stageW(Ws, w_up2, tid);
    if (tid < 64) sb[tid] = b_up2[tid];

    int tn = tid & 31, tm = tid >> 5;
    int c4 = tid & 63, rg = tid >> 6;
    int v4 = n0 + c4 * 4; if (v4 > V4 - 4) v4 = V4 - 4;
    int z0 = props[p * 7 + 1] >> 2, y0 = props[p * 7 + 2] >> 2, x0 = props[p * 7 + 3] >> 2;
    int d = v4 / 144; int r = v4 - d * 144; int hh = r / 12; int ww = r - hh * 12;
    long long base = (long long)(z0 + d) * 4096 + (y0 + hh) * 64 + (x0 + ww);

    // stage chunk 0
#pragma unroll
    for (int rr = 0; rr < 8; rr++) {
        int row = rg * 8 + rr;
        const float* gp = comb2 + (long long)row * NV2 + base;
        *(float4*)&Xs0[row * 256 + c4 * 4] =
            make_float4(__ldg(gp), __ldg(gp + 1), __ldg(gp + 2), __ldg(gp + 3));
    }
    __syncthreads();

    u64 acc[4][8];
#pragma unroll
    for (int i = 0; i < 4; i++) { int m = tm * 8 + 2 * i;
#pragma unroll
        for (int j = 0; j < 8; j++) acc[i][j] = pk2(sb[m], sb[m + 1]); }

#pragma unroll 1
    for (int kc = 0; kc < 4; kc++) {
        float* Xc = (kc & 1) ? Xs1 : Xs0;
        float* Xn = (kc & 1) ? Xs0 : Xs1;
        if (kc < 3) {
#pragma unroll
            for (int rr = 0; rr < 8; rr++) {
                int row = rg * 8 + rr;
                int c = (kc + 1) * 32 + row;
                const float* gp = comb2 + (long long)c * NV2 + base;
                *(float4*)&Xn[row * 256 + c4 * 4] =
                    make_float4(__ldg(gp), __ldg(gp + 1), __ldg(gp + 2), __ldg(gp + 3));
            }
        }
        mm32(Ws + kc * 32 * WSS, Xc, tm, tn, acc);
        __syncthreads();
    }

    float* Tb = g_T + (long long)(p * 64) * V4 + n0 + tn * 4;
#pragma unroll
    for (int i = 0; i < 4; i++) {
        int m = tm * 8 + 2 * i;
#pragma unroll
        for (int h = 0; h < 2; h++) {
            int n = n0 + h * 128 + tn * 4;
            if (n < V4) {
                float2 v0 = unpk2(acc[i][h * 4 + 0]), v1 = unpk2(acc[i][h * 4 + 1]);
                float2 v2 = unpk2(acc[i][h * 4 + 2]), v3 = unpk2(acc[i][h * 4 + 3]);
                *(float4*)(Tb + (long long)m * V4 + h * 128) = make_float4(v0.x, v1.x, v2.x, v3.x);
                *(float4*)(Tb + (long long)(m + 1) * V4 + h * 128) = make_float4(v0.y, v1.y, v2.y, v3.y);
            }
        }
    }
}

// ---------------- upsample 12->24 + U stats (LUT, row-per-thread) ----------------
__global__ __launch_bounds__(288) void k_upsample()
{
    int c = blockIdx.x, p = blockIdx.y;
    __shared__ float t[V4];
    __shared__ int   llo[24], lhi[24];
    __shared__ float lf[24];
    __shared__ float bs[9], bss[9];
    int tid = threadIdx.x;
    const float* tp = &g_T[(p * 64 + c) * V4];
    for (int i = tid; i < V4; i += 288) t[i] = tp[i];
    if (tid < 24) {
        int nd = tid * 11; int lo = nd / 23;
        llo[tid] = lo; lhi[tid] = min(lo + 1, 11);
        lf[tid] = (float)(nd - lo * 23) * (1.0f / 23.0f);
    }
    __syncthreads();

    float s = 0.f, ss = 0.f;
    float* up = &g_U[((long long)(p * 64 + c)) * Vc];
#pragma unroll
    for (int rep = 0; rep < 2; rep++) {
        int rrow = tid + rep * 288;          // 0..575 = d*24+h
        int d = rrow / 24; int h = rrow - d * 24;
        int ld = llo[d], hd = lhi[d]; float fd = lf[d];
        int lh = llo[h], hh = lhi[h]; float fh = lf[h];
        const float* p00 = t + ld * 144 + lh * 12;
        const float* p01 = t + ld * 144 + hh * 12;
        const float* p10 = t + hd * 144 + lh * 12;
        const float* p11 = t + hd * 144 + hh * 12;
        float rowc[12];
#pragma unroll
        for (int i = 0; i < 12; i++) {
            float a0 = p00[i], a1 = p01[i], b0 = p10[i], b1 = p11[i];
            float a = a0 + (a1 - a0) * fh;
            float b = b0 + (b1 - b0) * fh;
            rowc[i] = a + (b - a) * fd;
        }
        float outv[24];
#pragma unroll
        for (int w = 0; w < 24; w++) {
            const int nw = w * 11;
            const int lw = nw / 23;
            const int hw = (lw + 1 < 11) ? lw + 1 : 11;
            const float fw = (float)(nw - lw * 23) * (1.0f / 23.0f);
            float v = rowc[lw] + (rowc[hw] - rowc[lw]) * fw;
            outv[w] = v;
            s += v; ss = fmaf(v, v, ss);
        }
        float* o = up + rrow * 24;
#pragma unroll
        for (int q = 0; q < 6; q++)
            *(float4*)(o + q * 4) = make_float4(outv[q*4], outv[q*4+1], outv[q*4+2], outv[q*4+3]);
    }

    // block reduce (9 warps)
#pragma unroll
    for (int off = 16; off; off >>= 1) {
        s  += __shfl_down_sync(0xffffffffu, s,  off);
        ss += __shfl_down_sync(0xffffffffu, ss, off);
    }
    int wrp = tid >> 5, ln = tid & 31;
    if (ln == 0) { bs[wrp] = s; bss[wrp] = ss; }
    __syncthreads();
    if (wrp == 0) {
        s  = (ln < 9) ? bs[ln]  : 0.f;
        ss = (ln < 9) ? bss[ln] : 0.f;
#pragma unroll
        for (int off = 8; off; off >>= 1) {
            s  += __shfl_down_sync(0xffffffffu, s,  off);
            ss += __shfl_down_sync(0xffffffffu, ss, off);
        }
        if (ln == 0) { g_st1[(p * 64 + c) * 2] = s; g_st1[(p * 64 + c) * 2 + 1] = ss; }
    }
}

// ---------------- back2: tiled GEMM (double-buffered) + fused F-stats partials ----------------
constexpr int B2_FLOATS = 8448 + 8192 + 8192 + 192;
constexpr int B2_SMEM = B2_FLOATS * 4;
__global__ __launch_bounds__(256, 2) void k_back2t(
    const float* __restrict__ out1, const int* __restrict__ props,
    const float* __restrict__ w_back2, const float* __restrict__ b_back2,
    const float* __restrict__ gam, const float* __restrict__ bet)
{
    extern __shared__ float sm[];
    float* Ws = sm; float* Xs0 = sm + 8448; float* Xs1 = sm + 16640;
    float* sb = sm + 24832; float* sc = sb + 64; float* sh = sb + 128;
    int tid = threadIdx.x;
    int p = blockIdx.y, n0 = blockIdx.x * 256;

    stageW(Ws, w_back2, tid);
    if (tid < 64) {
        sb[tid] = b_back2[tid];
        float s = g_st1[(p * 64 + tid) * 2], q = g_st1[(p * 64 + tid) * 2 + 1];
        float mean = s * (1.f / Vc);
        float var = q * (1.f / Vc) - mean * mean;
        float a = gam[tid] * rsqrtf(var + EPSN);
        sc[tid] = a; sh[tid] = bet[tid] - mean * a;
    }

    int tn = tid & 31, tm = tid >> 5;
    int c4 = tid & 63, rg = tid >> 6;
    int v4 = n0 + c4 * 4;
    int z0 = props[p * 7 + 1] >> 1, y0 = props[p * 7 + 2] >> 1, x0 = props[p * 7 + 3] >> 1;
    int d = v4 / 576; int r = v4 - d * 576; int hh = r / 24; int ww = r - hh * 24;
    long long o1b = ((long long)(z0 + d) * 128 + (y0 + hh)) * 128 + (x0 + ww);
    const float* Ub = g_U + ((long long)p * 64) * Vc + v4;
    __syncthreads();   // sc/sh ready before staging chunk 0

    // stage chunk 0 (U channels 0..31)
#pragma unroll
    for (int rr = 0; rr < 8; rr++) {
        int row = rg * 8 + rr;
        float4 u = *(const float4*)(Ub + (long long)row * Vc);
        float a = sc[row], b = sh[row];
        *(float4*)&Xs0[row * 256 + c4 * 4] =
            make_float4(fmaxf(fmaf(u.x, a, b), 0.f), fmaxf(fmaf(u.y, a, b), 0.f),
                        fmaxf(fmaf(u.z, a, b), 0.f), fmaxf(fmaf(u.w, a, b), 0.f));
    }
    __syncthreads();

    u64 acc[4][8];
#pragma unroll
    for (int i = 0; i < 4; i++) { int m = tm * 8 + 2 * i;
#pragma unroll
        for (int j = 0; j < 8; j++) acc[i][j] = pk2(sb[m], sb[m + 1]); }

#pragma unroll 1
    for (int kc = 0; kc < 4; kc++) {
        float* Xc = (kc & 1) ? Xs1 : Xs0;
        float* Xn = (kc & 1) ? Xs0 : Xs1;
        if (kc == 0) {
#pragma unroll
            for (int rr = 0; rr < 8; rr++) {
                int row = rg * 8 + rr;
                int c = 32 + row;
                float4 u = *(const float4*)(Ub + (long long)c * Vc);
                float a = sc[c], b = sh[c];
                *(float4*)&Xn[row * 256 + c4 * 4] =
                    make_float4(fmaxf(fmaf(u.x, a, b), 0.f), fmaxf(fmaf(u.y, a, b), 0.f),
                                fmaxf(fmaf(u.z, a, b), 0.f), fmaxf(fmaf(u.w, a, b), 0.f));
            }
        } else if (kc < 3) {
#pragma unroll
            for (int rr = 0; rr < 8; rr++) {
                int row = rg * 8 + rr;
                int c = (kc - 1) * 32 + row;   // out1 channels
                const float* gp = out1 + (long long)c * C1STRIDE + o1b;
                float2 e0 = *(const float2*)(gp);
                float2 e1 = *(const float2*)(gp + 2);
                *(float4*)&Xn[row * 256 + c4 * 4] = make_float4(e0.x, e0.y, e1.x, e1.y);
            }
        }
        mm32(Ws + kc * 32 * WSS, Xc, tm, tn, acc);
        __syncthreads();
    }

    // epilogue: store F + warp-reduced per-channel partial stats
    float* Fb = g_F + ((long long)p * 64) * Vc + n0 + tn * 4;
    int pbase = (p * NB2 + blockIdx.x) * 64;
#pragma unroll
    for (int i = 0; i < 4; i++) {
        int m = tm * 8 + 2 * i;
        float sl = 0.f, ql = 0.f, sh2 = 0.f, qh = 0.f;
#pragma unroll
        for (int h = 0; h < 2; h++) {
            float2 v0 = unpk2(acc[i][h * 4 + 0]), v1 = unpk2(acc[i][h * 4 + 1]);
            float2 v2 = unpk2(acc[i][h * 4 + 2]), v3 = unpk2(acc[i][h * 4 + 3]);
            float4 lo = make_float4(v0.x, v1.x, v2.x, v3.x);
            float4 hi = make_float4(v0.y, v1.y, v2.y, v3.y);
            *(float4*)(Fb + (long long)m * Vc + h * 128) = lo;
            *(float4*)(Fb + (long long)(m + 1) * Vc + h * 128) = hi;
            sl += lo.x + lo.y + lo.z + lo.w;
            ql += lo.x * lo.x + lo.y * lo.y + lo.z * lo.z + lo.w * lo.w;
            sh2 += hi.x + hi.y + hi.z + hi.w;
            qh += hi.x * hi.x + hi.y * hi.y + hi.z * hi.z + hi.w * hi.w;
        }
#pragma unroll
        for (int off = 16; off; off >>= 1) {
            sl += __shfl_down_sync(0xffffffffu, sl, off);
            ql += __shfl_down_sync(0xffffffffu, ql, off);
            sh2 += __shfl_down_sync(0xffffffffu, sh2, off);
            qh += __shfl_down_sync(0xffffffffu, qh, off);
        }
        if (tn == 0) {
            g_spS[pbase + m] = sl;  g_spQ[pbase + m] = ql;
            g_spS[pbase + m + 1] = sh2; g_spQ[pbase + m + 1] = qh;
        }
    }
}

// ---------------- normalize + relu + 3^3 maxpool (stats inlined) ----------------
__global__ __launch_bounds__(512) void k_pool(
    const float* __restrict__ gam, const float* __restrict__ bet)
{
    int o = blockIdx.x, p = blockIdx.y;
    __shared__ float sS, sQ;
    if (threadIdx.x < 32) {
        float S = 0.f, Q = 0.f;
        for (int b2 = threadIdx.x; b2 < NB2; b2 += 32) {
            S += g_spS[(p * NB2 + b2) * 64 + o];
            Q += g_spQ[(p * NB2 + b2) * 64 + o];
        }
#pragma unroll
        for (int off = 16; off; off >>= 1) {
            S += __shfl_down_sync(0xffffffffu, S, off);
            Q += __shfl_down_sync(0xffffffffu, Q, off);
        }
        if (threadIdx.x == 0) { sS = S; sQ = Q; }
    }
    __syncthreads();
    float mean = sS * (1.f / Vc);
    float var = sQ * (1.f / Vc) - mean * mean;
    float a = gam[o] * rsqrtf(var + EPSN);
    float b = bet[o] - mean * a;

    int j = threadIdx.x;
    int od = j >> 6; int r = j & 63; int oh = r >> 3; int ow = r & 7;
    const float* Fp = &g_F[((long long)(p * 64 + o)) * Vc];
    float m = -1e30f;
#pragma unroll
    for (int dz = 0; dz < 3; dz++)
#pragma unroll
        for (int dy = 0; dy < 3; dy++)
#pragma unroll
            for (int dx = 0; dx < 3; dx++) {
                float v = Fp[(od * 3 + dz) * 576 + (oh * 3 + dy) * 24 + (ow * 3 + dx)];
                m = fmaxf(m, fmaxf(fmaf(v, a, b), 0.f));
            }
    g_CR[(p * 64 + o) * 512 + j] = m;
}

// ---------------- fc1 GEMM (K-split) ----------------
__global__ __launch_bounds__(256) void k_fc1(const float* __restrict__ w_fc1)
{
    __shared__ float Ws[64 * 65];
    __shared__ float Xs[64 * 65];
    int tid = threadIdx.x;
    int m0 = blockIdx.x * 64;
    int kb = blockIdx.y;
    int tp = tid & 63, tm = tid >> 6;

    float acc[16];
#pragma unroll
    for (int i = 0; i < 16; i++) acc[i] = 0.f;

    for (int ch = 0; ch < 32; ch++) {
        int k0 = kb * 2048 + ch * 64;
#pragma unroll
        for (int it = 0; it < 16; it++) {
            int idx = tid + it * 256;
            int kk = idx & 63, row = idx >> 6;
            Ws[row * 65 + kk] = w_fc1[(long long)(m0 + row) * 32768 + k0 + kk];
            Xs[kk * 65 + row] = g_CR[row * 32768 + k0 + kk];
        }
        __syncthreads();
#pragma unroll 8
        for (int k = 0; k < 64; k++) {
            float xv = Xs[k * 65 + tp];
#pragma unroll
            for (int i = 0; i < 16; i++) acc[i] = fmaf(Ws[(tm * 16 + i) * 65 + k], xv, acc[i]);
        }
        __syncthreads();
    }
    float* outp = &g_X1p[((long long)kb * 64 + tp) * 512 + m0 + tm * 16];
#pragma unroll
    for (int i = 0; i < 16; i++) outp[i] = acc[i];
}

__global__ __launch_bounds__(512) void k_fc1red(const float* __restrict__ b_fc1)
{
    int p = blockIdx.x; int m = threadIdx.x;
    float s = b_fc1[m];
#pragma unroll
    for (int kb = 0; kb < 16; kb++) s += g_X1p[((long long)kb * 64 + p) * 512 + m];
    g_X1[p * 512 + m] = fmaxf(s, 0.f);
}

// ---------------- fc2 + relu + rcnn heads (fused) ----------------
__global__ __launch_bounds__(256) void k_fc2h(
    const float* __restrict__ w_fc2, const float* __restrict__ b_fc2,
    const float* __restrict__ w_logit, const float* __restrict__ b_logit,
    const float* __restrict__ w_delta, const float* __restrict__ b_delta,
    float* __restrict__ out)
{
    int p = blockIdx.x; int o = threadIdx.x;
    __shared__ float xs[512];
    __shared__ float x2[256];
    for (int i = o; i < 512; i += 256) xs[i] = g_X1[p * 512 + i];
    __syncthreads();
    const float* wp = &w_fc2[o * 512];
    float s = b_fc2[o];
#pragma unroll 8
    for (int k = 0; k < 512; k++) s = fmaf(wp[k], xs[k], s);
    x2[o] = fmaxf(s, 0.f);
    __syncthreads();

    int w = o >> 5, ln = o & 31;
    const long long offL = (long long)NV2 * 21;
    for (int t = w; t < 14; t += 8) {
        const float* wt = (t < 2) ? &w_logit[t * 256] : &w_delta[(t - 2) * 256];
        float sv = 0.f;
        for (int k = ln; k < 256; k += 32) sv = fmaf(wt[k], x2[k], sv);
#pragma unroll
        for (int off = 16; off; off >>= 1) sv += __shfl_down_sync(0xffffffffu, sv, off);
        if (ln == 0) {
            if (t < 2) out[offL + p * 2 + t] = sv + b_logit[t];
            else       out[offL + 128 + p * 12 + (t - 2)] = sv + b_delta[t - 2];
        }
    }
}

// ---------------- launch ----------------
extern "C" void kernel_launch(void* const* d_in, const int* in_sizes, int n_in,
                              void* d_out, int out_size)
{
    const float* out1    = (const float*)d_in[0];
    const float* comb2   = (const float*)d_in[1];
    const int*   props   = (const int*)  d_in[2];
    const float* w_rpn   = (const float*)d_in[3];  const float* b_rpn   = (const float*)d_in[4];
    const float* w_rlog  = (const float*)d_in[5];  const float* b_rlog  = (const float*)d_in[6];
    const float* w_rdel  = (const float*)d_in[7];  const float* b_rdel  = (const float*)d_in[8];
    const float* w_up2   = (const float*)d_in[9];  const float* b_up2   = (const float*)d_in[10];
    const float* gu_up2  = (const float*)d_in[11]; const float* be_up2  = (const float*)d_in[12];
    const float* w_back2 = (const float*)d_in[13]; const float* b_back2 = (const float*)d_in[14];
    const float* gu_bk2  = (const float*)d_in[15]; const float* be_bk2  = (const float*)d_in[16];
    const float* w_fc1   = (const float*)d_in[17]; const float* b_fc1   = (const float*)d_in[18];
    const float* w_fc2   = (const float*)d_in[19]; const float* b_fc2   = (const float*)d_in[20];
    const float* w_logit = (const float*)d_in[21]; const float* b_logit = (const float*)d_in[22];
    const float* w_delta = (const float*)d_in[23]; const float* b_delta = (const float*)d_in[24];
    float* out = (float*)d_out;

    cudaFuncSetAttribute(k_rpn2, cudaFuncAttributeMaxDynamicSharedMemorySize, RPN_SMEM);
    cudaFuncSetAttribute(k_conv_low2, cudaFuncAttributeMaxDynamicSharedMemorySize, CL_SMEM);
    cudaFuncSetAttribute(k_back2t, cudaFuncAttributeMaxDynamicSharedMemorySize, B2_SMEM);

    k_rpn2<<<512, 256, RPN_SMEM>>>(comb2, w_rpn, b_rpn, w_rlog, b_rlog, w_rdel, b_rdel, out);
    k_conv_low2<<<dim3(7, P_), 256, CL_SMEM>>>(comb2, props, w_up2, b_up2);
    k_upsample<<<dim3(64, P_), 288>>>();
    k_back2t<<<dim3(NB2, P_), 256, B2_SMEM>>>(out1, props, w_back2, b_back2, gu_up2, be_up2);
    k_pool<<<dim3(64, P_), 512>>>(gu_bk2, be_bk2);
    k_fc1<<<dim3(8, 16), 256>>>(w_fc1);
    k_fc1red<<<P_, 512>>>(b_fc1);
    k_fc2h<<<P_, 256>>>(w_fc2, b_fc2, w_logit, b_logit, w_delta, b_delta, out);
}

// round 5
// speedup vs baseline: 2.0943x; 1.0862x over previous
#include <cuda_runtime.h>
#include <cstdint>

// ---------------- problem constants ----------------
constexpr int P_   = 64;
constexpr int NV2  = 32 * 64 * 64;        // comb2 voxels / channel stride
constexpr int C1STRIDE = 64 * 128 * 128;  // out1 channel stride
constexpr int V4 = 1728;                  // 12^3
constexpr int Vc = 13824;                 // 24^3
constexpr int NB2 = 54;                   // back2 n-tiles per proposal (13824/256)
constexpr int WSS = 66;                   // Ws row stride (pad vs bank conflicts)
constexpr float EPSN = 1e-5f;

typedef unsigned long long u64;

// ---------------- scratch ----------------
__device__ float g_T[P_ * 64 * V4];
__device__ float g_U[(long long)P_ * 64 * Vc];     // normalized+relu'd U
__device__ float g_F[(long long)P_ * 64 * Vc];
__device__ float g_spS[P_ * NB2 * 64];
__device__ float g_spQ[P_ * NB2 * 64];
__device__ float g_CR[P_ * 64 * 512];
__device__ float g_X1p[16 * P_ * 512];
__device__ float g_X1[P_ * 512];

// ---------------- f32x2 helpers ----------------
__device__ __forceinline__ u64 ffma2(u64 a, u64 b, u64 c) {
    u64 d; asm("fma.rn.f32x2 %0, %1, %2, %3;" : "=l"(d) : "l"(a), "l"(b), "l"(c)); return d;
}
__device__ __forceinline__ u64 pk2(float x, float y) {
    u64 d; asm("mov.b64 %0, {%1, %2};" : "=l"(d) : "f"(x), "f"(y)); return d;
}
__device__ __forceinline__ float2 unpk2(u64 v) {
    float2 r; asm("mov.b64 {%0, %1}, %2;" : "=f"(r.x), "=f"(r.y) : "l"(v)); return r;
}

// ---------------- cp.async helpers ----------------
__device__ __forceinline__ void cpa16(uint32_t dst, const float* src) {
    asm volatile("cp.async.cg.shared.global [%0], [%1], 16;\n" :: "r"(dst), "l"(src));
}
__device__ __forceinline__ void cpa8(uint32_t dst, const float* src) {
    asm volatile("cp.async.ca.shared.global [%0], [%1], 8;\n" :: "r"(dst), "l"(src));
}
__device__ __forceinline__ void cp_commit() {
    asm volatile("cp.async.commit_group;\n");
}
template<int N> __device__ __forceinline__ void cp_wait() {
    asm volatile("cp.async.wait_group %0;\n" :: "n"(N));
}

// stage W[64][128] (global, m-major) -> Ws[128][WSS] (k-major, padded)
__device__ __forceinline__ void stageW(float* Ws, const float* __restrict__ w, int tid) {
    int kg = (tid & 31) * 4;
    int mb = (tid >> 5) * 8;
#pragma unroll
    for (int mm = 0; mm < 8; mm++) {
        int m = mb + mm;
        float4 v = *(const float4*)(w + m * 128 + kg);
        Ws[(kg + 0) * WSS + m] = v.x;
        Ws[(kg + 1) * WSS + m] = v.y;
        Ws[(kg + 2) * WSS + m] = v.z;
        Ws[(kg + 3) * WSS + m] = v.w;
    }
}

// mainloop over one K=32 chunk
__device__ __forceinline__ void mm32(const float* WsK, const float* Xs,
                                     int tm, int tn, u64 acc[4][8]) {
#pragma unroll 8
    for (int k = 0; k < 32; k++) {
        const float* wp = WsK + k * WSS + tm * 8;
        u64 a0 = *(const u64*)(wp);
        u64 a1 = *(const u64*)(wp + 2);
        u64 a2 = *(const u64*)(wp + 4);
        u64 a3 = *(const u64*)(wp + 6);
        float4 xl = *(const float4*)(Xs + k * 256 + tn * 4);
        float4 xh = *(const float4*)(Xs + k * 256 + 128 + tn * 4);
        u64 a[4] = {a0, a1, a2, a3};
        u64 b[8] = {pk2(xl.x, xl.x), pk2(xl.y, xl.y), pk2(xl.z, xl.z), pk2(xl.w, xl.w),
                    pk2(xh.x, xh.x), pk2(xh.y, xh.y), pk2(xh.z, xh.z), pk2(xh.w, xh.w)};
#pragma unroll
        for (int i = 0; i < 4; i++)
#pragma unroll
            for (int j = 0; j < 8; j++) acc[i][j] = ffma2(a[i], b[j], acc[i][j]);
    }
}

// ---------------- RPN: tiled conv 128->64 + fused heads (cp.async pipelined) ----------------
constexpr int RPN_FLOATS = 8448 + 8192 + 8192 + 1344 + 24 + 64;
constexpr int RPN_SMEM = RPN_FLOATS * 4;
__global__ __launch_bounds__(256, 2) void k_rpn2(
    const float* __restrict__ comb2,
    const float* __restrict__ w_rpn, const float* __restrict__ b_rpn,
    const float* __restrict__ w_rlog, const float* __restrict__ b_rlog,
    const float* __restrict__ w_rdel, const float* __restrict__ b_rdel,
    float* __restrict__ out)
{
    extern __shared__ float sm[];
    float* Ws  = sm;                 // [0, 8448)
    float* Xs0 = sm + 8448;
    float* Xs1 = sm + 16640;
    float* wc  = sm + 24832;         // 1344
    float* bc  = wc + 1344;          // 24
    float* sb  = bc + 24;            // 64
    float* Hs  = sm;                 // reuse [0,16384) after mainloop
    int tid = threadIdx.x;
    int vox0 = blockIdx.x * 256;

    stageW(Ws, w_rpn, tid);
    for (int i = tid; i < 64 * 21; i += 256) {
        int o = i / 21, t = i - o * 21;
        wc[i] = (t < 3) ? w_rlog[t * 64 + o] : w_rdel[(t - 3) * 64 + o];
    }
    if (tid < 21) bc[tid] = (tid < 3) ? b_rlog[tid] : b_rdel[tid - 3];
    if (tid < 64) sb[tid] = b_rpn[tid];
    __syncthreads();

    int tn = tid & 31, tm = tid >> 5;
    int c4 = tid & 63, rg = tid >> 6;
    uint32_t sX0 = (uint32_t)__cvta_generic_to_shared(Xs0);
    uint32_t sX1 = (uint32_t)__cvta_generic_to_shared(Xs1);

    // prologue: stage chunk 0
#pragma unroll
    for (int rr = 0; rr < 8; rr++) {
        int row = rg * 8 + rr;
        cpa16(sX0 + (row * 256 + c4 * 4) * 4, comb2 + (long long)row * NV2 + vox0 + c4 * 4);
    }
    cp_commit();

    u64 acc[4][8];
#pragma unroll
    for (int i = 0; i < 4; i++) { int m = tm * 8 + 2 * i;
#pragma unroll
        for (int j = 0; j < 8; j++) acc[i][j] = pk2(sb[m], sb[m + 1]); }

#pragma unroll 1
    for (int kc = 0; kc < 4; kc++) {
        const float* Xc = (kc & 1) ? Xs1 : Xs0;
        uint32_t sXn = (kc & 1) ? sX0 : sX1;
        if (kc < 3) {
#pragma unroll
            for (int rr = 0; rr < 8; rr++) {
                int row = rg * 8 + rr;
                int c = (kc + 1) * 32 + row;
                cpa16(sXn + (row * 256 + c4 * 4) * 4, comb2 + (long long)c * NV2 + vox0 + c4 * 4);
            }
            cp_commit();
            cp_wait<1>();
        } else {
            cp_wait<0>();
        }
        __syncthreads();
        mm32(Ws + kc * 32 * WSS, Xc, tm, tn, acc);
        __syncthreads();
    }

    // store relu'd h into Hs[64][256]
#pragma unroll
    for (int i = 0; i < 4; i++) {
        int m = tm * 8 + 2 * i;
#pragma unroll
        for (int h = 0; h < 2; h++) {
            float2 v0 = unpk2(acc[i][h * 4 + 0]), v1 = unpk2(acc[i][h * 4 + 1]);
            float2 v2 = unpk2(acc[i][h * 4 + 2]), v3 = unpk2(acc[i][h * 4 + 3]);
            *(float4*)&Hs[m * 256 + h * 128 + tn * 4] =
                make_float4(fmaxf(v0.x, 0.f), fmaxf(v1.x, 0.f), fmaxf(v2.x, 0.f), fmaxf(v3.x, 0.f));
            *(float4*)&Hs[(m + 1) * 256 + h * 128 + tn * 4] =
                make_float4(fmaxf(v0.y, 0.f), fmaxf(v1.y, 0.f), fmaxf(v2.y, 0.f), fmaxf(v3.y, 0.f));
        }
    }
    __syncthreads();

    int vx = tid;
    float a[21];
#pragma unroll
    for (int t = 0; t < 21; t++) a[t] = bc[t];
    for (int o = 0; o < 64; o++) {
        float h = Hs[o * 256 + vx];
#pragma unroll
        for (int t = 0; t < 21; t++) a[t] = fmaf(wc[o * 21 + t], h, a[t]);
    }
    long long vox = vox0 + vx;
#pragma unroll
    for (int t = 0; t < 3; t++) out[vox * 3 + t] = a[t];
#pragma unroll
    for (int t = 0; t < 18; t++) out[(long long)NV2 * 3 + vox * 18 + t] = a[3 + t];
}

// ---------------- conv_low: up2 conv at 12^3 ----------------
constexpr int CL_FLOATS = 8448 + 8192 + 8192 + 64;
constexpr int CL_SMEM = CL_FLOATS * 4;
__global__ __launch_bounds__(256, 2) void k_conv_low2(
    const float* __restrict__ comb2, const int* __restrict__ props,
    const float* __restrict__ w_up2, const float* __restrict__ b_up2)
{
    extern __shared__ float sm[];
    float* Ws = sm; float* Xs0 = sm + 8448; float* Xs1 = sm + 16640;
    float* sb = sm + 24832;
    int tid = threadIdx.x;
    int p = blockIdx.y, n0 = blockIdx.x * 256;

    stageW(Ws, w_up2, tid);
    if (tid < 64) sb[tid] = b_up2[tid];

    int tn = tid & 31, tm = tid >> 5;
    int c4 = tid & 63, rg = tid >> 6;
    int v4 = n0 + c4 * 4; if (v4 > V4 - 4) v4 = V4 - 4;
    int z0 = props[p * 7 + 1] >> 2, y0 = props[p * 7 + 2] >> 2, x0 = props[p * 7 + 3] >> 2;
    int d = v4 / 144; int r = v4 - d * 144; int hh = r / 12; int ww = r - hh * 12;
    long long base = (long long)(z0 + d) * 4096 + (y0 + hh) * 64 + (x0 + ww);

#pragma unroll
    for (int rr = 0; rr < 8; rr++) {
        int row = rg * 8 + rr;
        const float* gp = comb2 + (long long)row * NV2 + base;
        *(float4*)&Xs0[row * 256 + c4 * 4] =
            make_float4(__ldg(gp), __ldg(gp + 1), __ldg(gp + 2), __ldg(gp + 3));
    }
    __syncthreads();

    u64 acc[4][8];
#pragma unroll
    for (int i = 0; i < 4; i++) { int m = tm * 8 + 2 * i;
#pragma unroll
        for (int j = 0; j < 8; j++) acc[i][j] = pk2(sb[m], sb[m + 1]); }

#pragma unroll 1
    for (int kc = 0; kc < 4; kc++) {
        float* Xc = (kc & 1) ? Xs1 : Xs0;
        float* Xn = (kc & 1) ? Xs0 : Xs1;
        if (kc < 3) {
#pragma unroll
            for (int rr = 0; rr < 8; rr++) {
                int row = rg * 8 + rr;
                int c = (kc + 1) * 32 + row;
                const float* gp = comb2 + (long long)c * NV2 + base;
                *(float4*)&Xn[row * 256 + c4 * 4] =
                    make_float4(__ldg(gp), __ldg(gp + 1), __ldg(gp + 2), __ldg(gp + 3));
            }
        }
        mm32(Ws + kc * 32 * WSS, Xc, tm, tn, acc);
        __syncthreads();
    }

    float* Tb = g_T + (long long)(p * 64) * V4 + n0 + tn * 4;
#pragma unroll
    for (int i = 0; i < 4; i++) {
        int m = tm * 8 + 2 * i;
#pragma unroll
        for (int h = 0; h < 2; h++) {
            int n = n0 + h * 128 + tn * 4;
            if (n < V4) {
                float2 v0 = unpk2(acc[i][h * 4 + 0]), v1 = unpk2(acc[i][h * 4 + 1]);
                float2 v2 = unpk2(acc[i][h * 4 + 2]), v3 = unpk2(acc[i][h * 4 + 3]);
                *(float4*)(Tb + (long long)m * V4 + h * 128) = make_float4(v0.x, v1.x, v2.x, v3.x);
                *(float4*)(Tb + (long long)(m + 1) * V4 + h * 128) = make_float4(v0.y, v1.y, v2.y, v3.y);
            }
        }
    }
}

// ---------------- upsample 12->24 + instnorm + relu (fully fused, in-register) ----------------
__global__ __launch_bounds__(288) void k_upsample(
    const float* __restrict__ gam, const float* __restrict__ bet)
{
    int c = blockIdx.x, p = blockIdx.y;
    __shared__ float t[V4];
    __shared__ int   llo[24], lhi[24];
    __shared__ float lf[24];
    __shared__ float bs[9], bss[9];
    __shared__ float sA, sB;
    int tid = threadIdx.x;
    const float* tp = &g_T[(p * 64 + c) * V4];
    for (int i = tid; i < V4; i += 288) t[i] = tp[i];
    if (tid < 24) {
        int nd = tid * 11; int lo = nd / 23;
        llo[tid] = lo; lhi[tid] = min(lo + 1, 11);
        lf[tid] = (float)(nd - lo * 23) * (1.0f / 23.0f);
    }
    __syncthreads();

    float s = 0.f, ss = 0.f;
    float outv[2][24];
#pragma unroll
    for (int rep = 0; rep < 2; rep++) {
        int rrow = tid + rep * 288;          // 0..575 = d*24+h
        int d = rrow / 24; int h = rrow - d * 24;
        int ld = llo[d], hd = lhi[d]; float fd = lf[d];
        int lh = llo[h], hh = lhi[h]; float fh = lf[h];
        const float* p00 = t + ld * 144 + lh * 12;
        const float* p01 = t + ld * 144 + hh * 12;
        const float* p10 = t + hd * 144 + lh * 12;
        const float* p11 = t + hd * 144 + hh * 12;
        float rowc[12];
#pragma unroll
        for (int i = 0; i < 12; i++) {
            float a0 = p00[i], a1 = p01[i], b0 = p10[i], b1 = p11[i];
            float a = a0 + (a1 - a0) * fh;
            float b = b0 + (b1 - b0) * fh;
            rowc[i] = a + (b - a) * fd;
        }
#pragma unroll
        for (int w = 0; w < 24; w++) {
            const int nw = w * 11;
            const int lw = nw / 23;
            const int hw = (lw + 1 < 11) ? lw + 1 : 11;
            const float fw = (float)(nw - lw * 23) * (1.0f / 23.0f);
            float v = rowc[lw] + (rowc[hw] - rowc[lw]) * fw;
            outv[rep][w] = v;
            s += v; ss = fmaf(v, v, ss);
        }
    }

    // block reduce + broadcast norm constants
#pragma unroll
    for (int off = 16; off; off >>= 1) {
        s  += __shfl_down_sync(0xffffffffu, s,  off);
        ss += __shfl_down_sync(0xffffffffu, ss, off);
    }
    int wrp = tid >> 5, ln = tid & 31;
    if (ln == 0) { bs[wrp] = s; bss[wrp] = ss; }
    __syncthreads();
    if (wrp == 0 && ln < 9) {
        s = bs[ln]; ss = bss[ln];
#pragma unroll
        for (int off = 8; off; off >>= 1) {
            s  += __shfl_down_sync(0x1ffu, s,  off);
            ss += __shfl_down_sync(0x1ffu, ss, off);
        }
        if (ln == 0) {
            float mean = s * (1.f / Vc);
            float var = ss * (1.f / Vc) - mean * mean;
            float a = gam[c] * rsqrtf(var + EPSN);
            sA = a; sB = bet[c] - mean * a;
        }
    }
    __syncthreads();
    float a = sA, b = sB;

    float* up = &g_U[((long long)(p * 64 + c)) * Vc];
#pragma unroll
    for (int rep = 0; rep < 2; rep++) {
        int rrow = tid + rep * 288;
        float* o = up + rrow * 24;
#pragma unroll
        for (int q = 0; q < 6; q++) {
            float v0 = fmaxf(fmaf(outv[rep][q*4+0], a, b), 0.f);
            float v1 = fmaxf(fmaf(outv[rep][q*4+1], a, b), 0.f);
            float v2 = fmaxf(fmaf(outv[rep][q*4+2], a, b), 0.f);
            float v3 = fmaxf(fmaf(outv[rep][q*4+3], a, b), 0.f);
            *(float4*)(o + q * 4) = make_float4(v0, v1, v2, v3);
        }
    }
}

// ---------------- back2: tiled GEMM (cp.async pipelined) + fused F-stats partials ----------------
constexpr int B2_FLOATS = 8448 + 8192 + 8192 + 64;
constexpr int B2_SMEM = B2_FLOATS * 4;
__global__ __launch_bounds__(256, 2) void k_back2t(
    const float* __restrict__ out1, const int* __restrict__ props,
    const float* __restrict__ w_back2, const float* __restrict__ b_back2)
{
    extern __shared__ float sm[];
    float* Ws = sm; float* Xs0 = sm + 8448; float* Xs1 = sm + 16640;
    float* sb = sm + 24832;
    int tid = threadIdx.x;
    int p = blockIdx.y, n0 = blockIdx.x * 256;

    stageW(Ws, w_back2, tid);
    if (tid < 64) sb[tid] = b_back2[tid];

    int tn = tid & 31, tm = tid >> 5;
    int c4 = tid & 63, rg = tid >> 6;
    int v4 = n0 + c4 * 4;
    int z0 = props[p * 7 + 1] >> 1, y0 = props[p * 7 + 2] >> 1, x0 = props[p * 7 + 3] >> 1;
    int d = v4 / 576; int r = v4 - d * 576; int hh = r / 24; int ww = r - hh * 24;
    long long o1b = ((long long)(z0 + d) * 128 + (y0 + hh)) * 128 + (x0 + ww);
    const float* Ub = g_U + ((long long)p * 64) * Vc + v4;
    __syncthreads();   // Ws/sb visible before first mm32; staging uses cp.async

    uint32_t sX0 = (uint32_t)__cvta_generic_to_shared(Xs0);
    uint32_t sX1 = (uint32_t)__cvta_generic_to_shared(Xs1);

    // prologue: stage chunk 0 (U channels 0..31) — pure copy
#pragma unroll
    for (int rr = 0; rr < 8; rr++) {
        int row = rg * 8 + rr;
        cpa16(sX0 + (row * 256 + c4 * 4) * 4, Ub + (long long)row * Vc);
    }
    cp_commit();

    u64 acc[4][8];
#pragma unroll
    for (int i = 0; i < 4; i++) { int m = tm * 8 + 2 * i;
#pragma unroll
        for (int j = 0; j < 8; j++) acc[i][j] = pk2(sb[m], sb[m + 1]); }

#pragma unroll 1
    for (int kc = 0; kc < 4; kc++) {
        const float* Xc = (kc & 1) ? Xs1 : Xs0;
        uint32_t sXn = (kc & 1) ? sX0 : sX1;
        if (kc == 0) {
#pragma unroll
            for (int rr = 0; rr < 8; rr++) {
                int row = rg * 8 + rr;
                cpa16(sXn + (row * 256 + c4 * 4) * 4, Ub + (long long)(32 + row) * Vc);
            }
            cp_commit();
            cp_wait<1>();
        } else if (kc < 3) {
#pragma unroll
            for (int rr = 0; rr < 8; rr++) {
                int row = rg * 8 + rr;
                int c = (kc - 1) * 32 + row;   // out1 channels (8B-aligned only)
                const float* gp = out1 + (long long)c * C1STRIDE + o1b;
                uint32_t ds = sXn + (row * 256 + c4 * 4) * 4;
                cpa8(ds, gp);
                cpa8(ds + 8, gp + 2);
            }
            cp_commit();
            cp_wait<1>();
        } else {
            cp_wait<0>();
        }
        __syncthreads();
        mm32(Ws + kc * 32 * WSS, Xc, tm, tn, acc);
        __syncthreads();
    }

    // epilogue: store F + warp-reduced per-channel partial stats
    float* Fb = g_F + ((long long)p * 64) * Vc + n0 + tn * 4;
    int pbase = (p * NB2 + blockIdx.x) * 64;
#pragma unroll
    for (int i = 0; i < 4; i++) {
        int m = tm * 8 + 2 * i;
        float sl = 0.f, ql = 0.f, sh2 = 0.f, qh = 0.f;
#pragma unroll
        for (int h = 0; h < 2; h++) {
            float2 v0 = unpk2(acc[i][h * 4 + 0]), v1 = unpk2(acc[i][h * 4 + 1]);
            float2 v2 = unpk2(acc[i][h * 4 + 2]), v3 = unpk2(acc[i][h * 4 + 3]);
            float4 lo = make_float4(v0.x, v1.x, v2.x, v3.x);
            float4 hi = make_float4(v0.y, v1.y, v2.y, v3.y);
            *(float4*)(Fb + (long long)m * Vc + h * 128) = lo;
            *(float4*)(Fb + (long long)(m + 1) * Vc + h * 128) = hi;
            sl += lo.x + lo.y + lo.z + lo.w;
            ql += lo.x * lo.x + lo.y * lo.y + lo.z * lo.z + lo.w * lo.w;
            sh2 += hi.x + hi.y + hi.z + hi.w;
            qh += hi.x * hi.x + hi.y * hi.y + hi.z * hi.z + hi.w * hi.w;
        }
#pragma unroll
        for (int off = 16; off; off >>= 1) {
            sl += __shfl_down_sync(0xffffffffu, sl, off);
            ql += __shfl_down_sync(0xffffffffu, ql, off);
            sh2 += __shfl_down_sync(0xffffffffu, sh2, off);
            qh += __shfl_down_sync(0xffffffffu, qh, off);
        }
        if (tn == 0) {
            g_spS[pbase + m] = sl;  g_spQ[pbase + m] = ql;
            g_spS[pbase + m + 1] = sh2; g_spQ[pbase + m + 1] = qh;
        }
    }
}

// ---------------- normalize + relu + 3^3 maxpool (stats inlined) ----------------
__global__ __launch_bounds__(512) void k_pool(
    const float* __restrict__ gam, const float* __restrict__ bet)
{
    int o = blockIdx.x, p = blockIdx.y;
    __shared__ float sS, sQ;
    if (threadIdx.x < 32) {
        float S = 0.f, Q = 0.f;
        for (int b2 = threadIdx.x; b2 < NB2; b2 += 32) {
            S += g_spS[(p * NB2 + b2) * 64 + o];
            Q += g_spQ[(p * NB2 + b2) * 64 + o];
        }
#pragma unroll
        for (int off = 16; off; off >>= 1) {
            S += __shfl_down_sync(0xffffffffu, S, off);
            Q += __shfl_down_sync(0xffffffffu, Q, off);
        }
        if (threadIdx.x == 0) { sS = S; sQ = Q; }
    }
    __syncthreads();
    float mean = sS * (1.f / Vc);
    float var = sQ * (1.f / Vc) - mean * mean;
    float a = gam[o] * rsqrtf(var + EPSN);
    float b = bet[o] - mean * a;

    int j = threadIdx.x;
    int od = j >> 6; int r = j & 63; int oh = r >> 3; int ow = r & 7;
    const float* Fp = &g_F[((long long)(p * 64 + o)) * Vc];
    float m = -1e30f;
#pragma unroll
    for (int dz = 0; dz < 3; dz++)
#pragma unroll
        for (int dy = 0; dy < 3; dy++)
#pragma unroll
            for (int dx = 0; dx < 3; dx++) {
                float v = Fp[(od * 3 + dz) * 576 + (oh * 3 + dy) * 24 + (ow * 3 + dx)];
                m = fmaxf(m, fmaxf(fmaf(v, a, b), 0.f));
            }
    g_CR[(p * 64 + o) * 512 + j] = m;
}

// ---------------- fc1 GEMM (K-split) ----------------
__global__ __launch_bounds__(256) void k_fc1(const float* __restrict__ w_fc1)
{
    __shared__ float Ws[64 * 65];
    __shared__ float Xs[64 * 65];
    int tid = threadIdx.x;
    int m0 = blockIdx.x * 64;
    int kb = blockIdx.y;
    int tp = tid & 63, tm = tid >> 6;

    float acc[16];
#pragma unroll
    for (int i = 0; i < 16; i++) acc[i] = 0.f;

    for (int ch = 0; ch < 32; ch++) {
        int k0 = kb * 2048 + ch * 64;
#pragma unroll
        for (int it = 0; it < 16; it++) {
            int idx = tid + it * 256;
            int kk = idx & 63, row = idx >> 6;
            Ws[row * 65 + kk] = w_fc1[(long long)(m0 + row) * 32768 + k0 + kk];
            Xs[kk * 65 + row] = g_CR[row * 32768 + k0 + kk];
        }
        __syncthreads();
#pragma unroll 8
        for (int k = 0; k < 64; k++) {
            float xv = Xs[k * 65 + tp];
#pragma unroll
            for (int i = 0; i < 16; i++) acc[i] = fmaf(Ws[(tm * 16 + i) * 65 + k], xv, acc[i]);
        }
        __syncthreads();
    }
    float* outp = &g_X1p[((long long)kb * 64 + tp) * 512 + m0 + tm * 16];
#pragma unroll
    for (int i = 0; i < 16; i++) outp[i] = acc[i];
}

__global__ __launch_bounds__(512) void k_fc1red(const float* __restrict__ b_fc1)
{
    int p = blockIdx.x; int m = threadIdx.x;
    float s = b_fc1[m];
#pragma unroll
    for (int kb = 0; kb < 16; kb++) s += g_X1p[((long long)kb * 64 + p) * 512 + m];
    g_X1[p * 512 + m] = fmaxf(s, 0.f);
}

// ---------------- fc2 + relu + rcnn heads (fused) ----------------
__global__ __launch_bounds__(256) void k_fc2h(
    const float* __restrict__ w_fc2, const float* __restrict__ b_fc2,
    const float* __restrict__ w_logit, const float* __restrict__ b_logit,
    const float* __restrict__ w_delta, const float* __restrict__ b_delta,
    float* __restrict__ out)
{
    int p = blockIdx.x; int o = threadIdx.x;
    __shared__ float xs[512];
    __shared__ float x2[256];
    for (int i = o; i < 512; i += 256) xs[i] = g_X1[p * 512 + i];
    __syncthreads();
    const float* wp = &w_fc2[o * 512];
    float s = b_fc2[o];
#pragma unroll 8
    for (int k = 0; k < 512; k++) s = fmaf(wp[k], xs[k], s);
    x2[o] = fmaxf(s, 0.f);
    __syncthreads();

    int w = o >> 5, ln = o & 31;
    const long long offL = (long long)NV2 * 21;
    for (int t = w; t < 14; t += 8) {
        const float* wt = (t < 2) ? &w_logit[t * 256] : &w_delta[(t - 2) * 256];
        float sv = 0.f;
        for (int k = ln; k < 256; k += 32) sv = fmaf(wt[k], x2[k], sv);
#pragma unroll
        for (int off = 16; off; off >>= 1) sv += __shfl_down_sync(0xffffffffu, sv, off);
        if (ln == 0) {
            if (t < 2) out[offL + p * 2 + t] = sv + b_logit[t];
            else       out[offL + 128 + p * 12 + (t - 2)] = sv + b_delta[t - 2];
        }
    }
}

// ---------------- launch ----------------
extern "C" void kernel_launch(void* const* d_in, const int* in_sizes, int n_in,
                              void* d_out, int out_size)
{
    const float* out1    = (const float*)d_in[0];
    const float* comb2   = (const float*)d_in[1];
    const int*   props   = (const int*)  d_in[2];
    const float* w_rpn   = (const float*)d_in[3];  const float* b_rpn   = (const float*)d_in[4];
    const float* w_rlog  = (const float*)d_in[5];  const float* b_rlog  = (const float*)d_in[6];
    const float* w_rdel  = (const float*)d_in[7];  const float* b_rdel  = (const float*)d_in[8];
    const float* w_up2   = (const float*)d_in[9];  const float* b_up2   = (const float*)d_in[10];
    const float* gu_up2  = (const float*)d_in[11]; const float* be_up2  = (const float*)d_in[12];
    const float* w_back2 = (const float*)d_in[13]; const float* b_back2 = (const float*)d_in[14];
    const float* gu_bk2  = (const float*)d_in[15]; const float* be_bk2  = (const float*)d_in[16];
    const float* w_fc1   = (const float*)d_in[17]; const float* b_fc1   = (const float*)d_in[18];
    const float* w_fc2   = (const float*)d_in[19]; const float* b_fc2   = (const float*)d_in[20];
    const float* w_logit = (const float*)d_in[21]; const float* b_logit = (const float*)d_in[22];
    const float* w_delta = (const float*)d_in[23]; const float* b_delta = (const float*)d_in[24];
    float* out = (float*)d_out;

    cudaFuncSetAttribute(k_rpn2, cudaFuncAttributeMaxDynamicSharedMemorySize, RPN_SMEM);
    cudaFuncSetAttribute(k_conv_low2, cudaFuncAttributeMaxDynamicSharedMemorySize, CL_SMEM);
    cudaFuncSetAttribute(k_back2t, cudaFuncAttributeMaxDynamicSharedMemorySize, B2_SMEM);

    k_rpn2<<<512, 256, RPN_SMEM>>>(comb2, w_rpn, b_rpn, w_rlog, b_rlog, w_rdel, b_rdel, out);
    k_conv_low2<<<dim3(7, P_), 256, CL_SMEM>>>(comb2, props, w_up2, b_up2);
    k_upsample<<<dim3(64, P_), 288>>>(gu_up2, be_up2);
    k_back2t<<<dim3(NB2, P_), 256, B2_SMEM>>>(out1, props, w_back2, b_back2);
    k_pool<<<dim3(64, P_), 512>>>(gu_bk2, be_bk2);
    k_fc1<<<dim3(8, 16), 256>>>(w_fc1);
    k_fc1red<<<P_, 512>>>(b_fc1);
    k_fc2h<<<P_, 256>>>(w_fc2, b_fc2, w_logit, b_logit, w_delta, b_delta, out);
}